// round 13
// baseline (speedup 1.0000x reference)
#include <cuda_runtime.h>
#include <math.h>
#include <cstdint>

// Shapes (fixed by the problem)
#define B_    2
#define I_    8
#define J_    1025
#define M_    256
#define H_    8
#define DH_   32
#define NSLAB 16              // B_*I_
#define RTOT  (NSLAB * J_)    // 16400
#define FF_   1024            // 4*M
#define NCH   5               // gram J-chunks
#define MM_   (M_ * M_)

typedef unsigned long long u64;

// ---- scratch (static __device__ arrays; no runtime allocation) ----
__device__ float g_sln[RTOT * M_];
__device__ float g_s2 [RTOT * M_];
__device__ float g_hln[RTOT * M_];
__device__ float g_h1 [(size_t)RTOT * FF_];
__device__ float g_G  [NSLAB * MM_];
__device__ float g_Gp [NCH * NSLAB * MM_];     // gram partials
__device__ float g_T  [NSLAB * MM_];
__device__ float g_ET [NSLAB * MM_];
__device__ float g_wosum[M_];

// ---- f32x2 packed-FMA helpers ----
__device__ __forceinline__ u64 dup2(float x) {
    u64 r; asm("mov.b64 %0, {%1,%1};" : "=l"(r) : "f"(x)); return r;
}
__device__ __forceinline__ void fma2(u64& d, u64 a, u64 b) {
    asm("fma.rn.f32x2 %0, %1, %2, %0;" : "+l"(d) : "l"(a), "l"(b));
}
__device__ __forceinline__ float2 unpack2(u64 v) {
    float2 r; asm("mov.b64 {%0,%1}, %2;" : "=f"(r.x), "=f"(r.y) : "l"(v)); return r;
}

// ---- bf16 mma helper (m16n8k16, sm_80+) ----
__device__ __forceinline__ void mma_bf16(float* c,
    uint32_t a0, uint32_t a1, uint32_t a2, uint32_t a3,
    uint32_t b0, uint32_t b1)
{
    asm("mma.sync.aligned.m16n8k16.row.col.f32.bf16.bf16.f32 "
        "{%0,%1,%2,%3}, {%4,%5,%6,%7}, {%8,%9}, {%0,%1,%2,%3};"
        : "+f"(c[0]), "+f"(c[1]), "+f"(c[2]), "+f"(c[3])
        : "r"(a0), "r"(a1), "r"(a2), "r"(a3), "r"(b0), "r"(b1));
}
__device__ __forceinline__ uint32_t pack_lo2(float lo0, float lo1) {
    uint32_t r;
    asm("cvt.rn.bf16x2.f32 %0, %1, %2;" : "=r"(r) : "f"(lo1), "f"(lo0));
    return r;
}

// ============================================================
// LayerNorm over last dim M_=256, one block (256 thr) per row
// ============================================================
__global__ void ln_kernel(const float* __restrict__ x,
                          const float* __restrict__ g,
                          const float* __restrict__ b,
                          float* __restrict__ out)
{
    int row = blockIdx.x;
    const float* xr = x + (size_t)row * M_;
    int t = threadIdx.x;
    float v = xr[t];

    __shared__ float sm[8];
    float s = v;
    #pragma unroll
    for (int o = 16; o > 0; o >>= 1) s += __shfl_xor_sync(0xffffffffu, s, o);
    if ((t & 31) == 0) sm[t >> 5] = s;
    __syncthreads();
    float mean = 0.f;
    #pragma unroll
    for (int i = 0; i < 8; i++) mean += sm[i];
    mean *= (1.0f / M_);
    __syncthreads();
    float d = v - mean;
    float q = d * d;
    #pragma unroll
    for (int o = 16; o > 0; o >>= 1) q += __shfl_xor_sync(0xffffffffu, q, o);
    if ((t & 31) == 0) sm[t >> 5] = q;
    __syncthreads();
    float var = 0.f;
    #pragma unroll
    for (int i = 0; i < 8; i++) var += sm[i];
    var *= (1.0f / M_);

    out[(size_t)row * M_ + t] = d * rsqrtf(var + 1e-5f) * g[t] + b[t];
}

// ============================================================
// Wo row sums — one warp per row
// ============================================================
__global__ void rowsum_kernel(const float* __restrict__ Wo, float* __restrict__ ws)
{
    int warp = threadIdx.x >> 5, lane = threadIdx.x & 31;
    int n = blockIdx.x * 8 + warp;
    const float* row = Wo + (size_t)n * M_;
    float s = 0.f;
    #pragma unroll
    for (int m = lane; m < M_; m += 32) s += row[m];
    #pragma unroll
    for (int o = 16; o > 0; o >>= 1) s += __shfl_xor_sync(0xffffffffu, s, o);
    if (lane == 0) ws[n] = s;
}

// ============================================================
// Gram partials: J split in NCH chunks
// ============================================================
__global__ void __launch_bounds__(256) gram_kernel(const float* __restrict__ sln,
                                                   float* __restrict__ Gp)
{
    if (blockIdx.y < blockIdx.x) return;
    int zc = blockIdx.z;
    int slab = zc / NCH;
    int ch = zc - slab * NCH;
    const float* A = sln + (size_t)slab * J_ * M_;
    int p0 = blockIdx.x * 64, q0 = blockIdx.y * 64;

    int t0 = ch * 13, t1 = t0 + 13;

    __shared__ float As[2][16][64], Bs[2][16][64];
    int tid = threadIdx.x;
    int jj = tid >> 4;
    int cq = (tid & 15) << 2;
    int tx = tid & 15, ty = tid >> 4;

    float4 av, bv;
    {
        int j = t0 * 16 + jj;
        if (j < J_) {
            av = *(const float4*)(A + (size_t)j * M_ + p0 + cq);
            bv = *(const float4*)(A + (size_t)j * M_ + q0 + cq);
        } else { av = make_float4(0.f,0.f,0.f,0.f); bv = av; }
    }
    *(float4*)&As[0][jj][cq] = av;
    *(float4*)&Bs[0][jj][cq] = bv;
    __syncthreads();

    u64 acc[4][2] = {};
    for (int it = t0; it < t1; it++) {
        int cur = (it - t0) & 1;
        float4 nav, nbv;
        bool more = (it + 1 < t1);
        if (more) {
            int j = (it + 1) * 16 + jj;
            if (j < J_) {
                nav = *(const float4*)(A + (size_t)j * M_ + p0 + cq);
                nbv = *(const float4*)(A + (size_t)j * M_ + q0 + cq);
            } else { nav = make_float4(0.f,0.f,0.f,0.f); nbv = nav; }
        }
        #pragma unroll
        for (int k = 0; k < 16; k++) {
            float4 a = *(const float4*)&As[cur][k][ty << 2];
            ulonglong2 b = *(const ulonglong2*)&Bs[cur][k][tx << 2];
            u64 a2;
            a2 = dup2(a.x); fma2(acc[0][0], a2, b.x); fma2(acc[0][1], a2, b.y);
            a2 = dup2(a.y); fma2(acc[1][0], a2, b.x); fma2(acc[1][1], a2, b.y);
            a2 = dup2(a.z); fma2(acc[2][0], a2, b.x); fma2(acc[2][1], a2, b.y);
            a2 = dup2(a.w); fma2(acc[3][0], a2, b.x); fma2(acc[3][1], a2, b.y);
        }
        if (more) {
            *(float4*)&As[cur ^ 1][jj][cq] = nav;
            *(float4*)&Bs[cur ^ 1][jj][cq] = nbv;
        }
        __syncthreads();
    }
    float* Gs = Gp + (size_t)zc * MM_;
    #pragma unroll
    for (int i = 0; i < 4; i++) {
        int p = p0 + (ty << 2) + i;
        #pragma unroll
        for (int j2 = 0; j2 < 2; j2++) {
            float2 v = unpack2(acc[i][j2]);
            int q = q0 + (tx << 2) + j2 * 2;
            Gs[(size_t)p * M_ + q]     = v.x;
            Gs[(size_t)p * M_ + q + 1] = v.y;
            Gs[(size_t)q * M_ + p]       = v.x;
            Gs[(size_t)(q + 1) * M_ + p] = v.y;
        }
    }
}

// ============================================================
// Gram reduce
// ============================================================
__global__ void gram_reduce(const float* __restrict__ Gp, float* __restrict__ G)
{
    int slab = blockIdx.y;
    int idx = (blockIdx.x * 256 + threadIdx.x) * 4;
    const float* base = Gp + (size_t)slab * NCH * MM_ + idx;
    float4 s = *(const float4*)base;
    #pragma unroll
    for (int ch = 1; ch < NCH; ch++) {
        float4 v = *(const float4*)(base + (size_t)ch * MM_);
        s.x += v.x; s.y += v.y; s.z += v.z; s.w += v.w;
    }
    *(float4*)(G + (size_t)slab * MM_ + idx) = s;
}

// ============================================================
// 64x64 NT GEMM (T = G @ Wv^T)
// ============================================================
__global__ void __launch_bounds__(256) gemm64(
    const float* __restrict__ Ab, int lda, long aStride,
    const float* __restrict__ Bb, int ldb, long bStride,
    float* __restrict__ Cb, int ldc, long cStride, int K)
{
    int slab = blockIdx.z;
    const float* A = Ab + (size_t)slab * aStride;
    const float* B = Bb + (size_t)slab * bStride;
    float*       C = Cb + (size_t)slab * cStride;

    int rowBase = blockIdx.x * 64;
    int colBase = blockIdx.y * 64;

    __shared__ float As[16][64], Bs[16][64];
    int tid = threadIdx.x;
    int lm = tid >> 2;
    int lk = (tid & 3) << 2;
    int tx = tid & 15, ty = tid >> 4;

    u64 acc[4][2] = {};
    for (int k0 = 0; k0 < K; k0 += 16) {
        float4 av = *(const float4*)(A + (size_t)(rowBase + lm) * lda + k0 + lk);
        As[lk + 0][lm] = av.x; As[lk + 1][lm] = av.y;
        As[lk + 2][lm] = av.z; As[lk + 3][lm] = av.w;
        float4 bv = *(const float4*)(B + (size_t)(colBase + lm) * ldb + k0 + lk);
        Bs[lk + 0][lm] = bv.x; Bs[lk + 1][lm] = bv.y;
        Bs[lk + 2][lm] = bv.z; Bs[lk + 3][lm] = bv.w;
        __syncthreads();
        #pragma unroll
        for (int k = 0; k < 16; k++) {
            float4 a = *(const float4*)&As[k][ty << 2];
            ulonglong2 b = *(const ulonglong2*)&Bs[k][tx << 2];
            u64 a2;
            a2 = dup2(a.x); fma2(acc[0][0], a2, b.x); fma2(acc[0][1], a2, b.y);
            a2 = dup2(a.y); fma2(acc[1][0], a2, b.x); fma2(acc[1][1], a2, b.y);
            a2 = dup2(a.z); fma2(acc[2][0], a2, b.x); fma2(acc[2][1], a2, b.y);
            a2 = dup2(a.w); fma2(acc[3][0], a2, b.x); fma2(acc[3][1], a2, b.y);
        }
        __syncthreads();
    }
    #pragma unroll
    for (int i = 0; i < 4; i++) {
        int r = rowBase + (ty << 2) + i;
        #pragma unroll
        for (int j2 = 0; j2 < 2; j2++) {
            int c = colBase + (tx << 2) + j2 * 2;
            float2 v = unpack2(acc[i][j2]);
            *(float2*)(C + (size_t)r * ldc + c) = v;
        }
    }
}

// ============================================================
// Small per-(head,slab) finisher
// ============================================================
__global__ void __launch_bounds__(256) assemble2_kernel(const float* __restrict__ Wqkv,
                                                        const float* __restrict__ T,
                                                        float* __restrict__ ET)
{
    int h = blockIdx.x;
    int slab = blockIdx.y;
    const float* Ts = T + (size_t)slab * MM_;
    const float* Wq = Wqkv + (size_t)(0 * H_ + h) * DH_ * M_;
    const float* Wk = Wqkv + (size_t)(1 * H_ + h) * DH_ * M_;

    __shared__ float sT[256][33];
    __shared__ float ktv[32][33];
    int tid = threadIdx.x;

    {
        int m = tid >> 5, d = tid & 31;
        #pragma unroll
        for (int pass = 0; pass < 32; pass++) {
            int mm = pass * 8 + m;
            sT[mm][d] = Ts[(size_t)mm * M_ + h * 32 + d];
        }
    }
    __syncthreads();

    {
        int d  = tid & 31;
        int e0 = (tid >> 5) << 2;
        float acc4[4] = {0.f, 0.f, 0.f, 0.f};
        for (int m = 0; m < 256; m++) {
            float t = sT[m][d];
            #pragma unroll
            for (int ee = 0; ee < 4; ee++)
                acc4[ee] = fmaf(Wk[(size_t)(e0 + ee) * M_ + m], t, acc4[ee]);
        }
        #pragma unroll
        for (int ee = 0; ee < 4; ee++)
            ktv[e0 + ee][d] = acc4[ee];
    }
    __syncthreads();

    float acc3[32];
    #pragma unroll
    for (int d = 0; d < 32; d++) acc3[d] = 0.f;
    for (int e2 = 0; e2 < 32; e2++) {
        float w = Wq[(size_t)e2 * M_ + tid];
        #pragma unroll
        for (int d = 0; d < 32; d++) acc3[d] = fmaf(w, ktv[e2][d], acc3[d]);
    }
    const float scale = 0.17677669529663687f;
    float* ETs = ET + (size_t)slab * MM_;
    #pragma unroll
    for (int d = 0; d < 32; d++)
        ETs[(size_t)(h * 32 + d) * M_ + tid] = scale * acc3[d];
}

// ============================================================
// 3-product split-bf16 tensor-core NT GEMM (m16n8k16).
// 512 threads / 16 warps per CTA; 32x32 per warp (4x4 warp grid
// over a 128x128 CTA tile). Threads 0-255 load A (2/row, float8),
// threads 256-511 load B — same smem layout as the validated
// 256-thread version:
//   row (16 u32 + 4 pad): groups q=[hi_2q, hi_2q+1, lo_2q, lo_2q+1]
//   mode 0: C = acc * e1[c] + e2[slab][r,c]     (s2; batched)
//   mode 1: C = gelu(acc + e1[c])               (fc1)
//   mode 2: C = acc + e1[c] + e2[r,c]           (fc2 + resid)
// ============================================================
#define ST 20
__device__ __forceinline__ void split_store8(uint32_t* rowp, int woff,
                                             float4 f0, float4 f1)
{
    uint32_t u0 = __float_as_uint(f0.x), u1 = __float_as_uint(f0.y);
    uint32_t u2 = __float_as_uint(f0.z), u3 = __float_as_uint(f0.w);
    uint32_t u4 = __float_as_uint(f1.x), u5 = __float_as_uint(f1.y);
    uint32_t u6 = __float_as_uint(f1.z), u7 = __float_as_uint(f1.w);
    uint32_t h01 = __byte_perm(u0, u1, 0x7632);
    uint32_t h23 = __byte_perm(u2, u3, 0x7632);
    uint32_t h45 = __byte_perm(u4, u5, 0x7632);
    uint32_t h67 = __byte_perm(u6, u7, 0x7632);
    uint32_t l01 = pack_lo2(f0.x - __uint_as_float(u0 & 0xFFFF0000u),
                            f0.y - __uint_as_float(u1 & 0xFFFF0000u));
    uint32_t l23 = pack_lo2(f0.z - __uint_as_float(u2 & 0xFFFF0000u),
                            f0.w - __uint_as_float(u3 & 0xFFFF0000u));
    uint32_t l45 = pack_lo2(f1.x - __uint_as_float(u4 & 0xFFFF0000u),
                            f1.y - __uint_as_float(u5 & 0xFFFF0000u));
    uint32_t l67 = pack_lo2(f1.z - __uint_as_float(u6 & 0xFFFF0000u),
                            f1.w - __uint_as_float(u7 & 0xFFFF0000u));
    *(uint4*)(rowp + woff)     = make_uint4(h01, h23, l01, l23);
    *(uint4*)(rowp + woff + 4) = make_uint4(h45, h67, l45, l67);
}

__global__ void __launch_bounds__(512) bf16_gemm(
    const float* __restrict__ Ab, int lda, long aStr,
    const float* __restrict__ Bb, int ldb, long bStr,
    float* __restrict__ Cb, int ldc, long cStr,
    int K, int Rlim, int mode,
    const float* __restrict__ e1,
    const float* __restrict__ e2b, long e2Str)
{
    __shared__ uint32_t sA[2][128 * ST], sB[2][128 * ST];   // 40 KB
    int tid = threadIdx.x;
    int slab = blockIdx.z;
    const float* A = Ab + (size_t)slab * aStr;
    const float* B = Bb + (size_t)slab * bStr;
    float*       C = Cb + (size_t)slab * cStr;
    const float* E2 = e2b ? (e2b + (size_t)slab * e2Str) : (const float*)0;

    int rowBase = blockIdx.x * 128, colBase = blockIdx.y * 128;

    // loader role: threads 0-255 -> A, 256-511 -> B (R11 pattern each)
    int lt    = tid & 255;
    int ldRow = lt >> 1;             // 0..127
    int ldK   = (lt & 1) << 3;       // 0 or 8
    int woff  = (lt & 1) << 3;       // word offset 0 or 8
    bool isA  = tid < 256;
    const float* src = isA
        ? (A + (size_t)(rowBase + ldRow) * lda + ldK)
        : (B + (size_t)(colBase + ldRow) * ldb + ldK);
    bool lValid = isA ? ((rowBase + ldRow) < Rlim) : true;
    uint32_t* dstBuf0 = isA ? &sA[0][ldRow * ST] : &sB[0][ldRow * ST];
    uint32_t* dstBuf1 = isA ? &sA[1][ldRow * ST] : &sB[1][ldRow * ST];

    int lane = tid & 31, warp = tid >> 5;       // 16 warps
    int wRow = (warp >> 2) << 5;     // 0,32,64,96
    int wCol = (warp & 3) << 5;      // 0,32,64,96
    int g = lane >> 2, t = lane & 3;

    const int NT = K >> 4;
    const float4 z4 = make_float4(0.f, 0.f, 0.f, 0.f);

    // preload tile 0
    {
        float4 v0 = lValid ? *(const float4*)src : z4;
        float4 v1 = lValid ? *(const float4*)(src + 4) : z4;
        split_store8(dstBuf0, woff, v0, v1);
    }
    __syncthreads();

    float acc[2][4][4];
    #pragma unroll
    for (int i = 0; i < 2; i++)
        #pragma unroll
        for (int j = 0; j < 4; j++)
            #pragma unroll
            for (int q = 0; q < 4; q++) acc[i][j][q] = 0.f;

    for (int it = 0; it < NT; it++) {
        int cur = it & 1;
        bool more = (it + 1 < NT);
        float4 n0, n1;
        if (more) {
            int k0 = (it + 1) << 4;
            n0 = lValid ? *(const float4*)(src + k0) : z4;
            n1 = lValid ? *(const float4*)(src + k0 + 4) : z4;
        }

        const uint32_t* sa = sA[cur];
        const uint32_t* sb = sB[cur];

        // B fragments once: 4x LDS.128
        uint4 bv[4];
        #pragma unroll
        for (int nb = 0; nb < 4; nb++)
            bv[nb] = *(const uint4*)(sb + (wCol + (nb << 3) + g) * ST + (t << 2));

        // A fragments per mb (2 m16 blocks)
        #pragma unroll
        for (int mb = 0; mb < 2; mb++) {
            const uint32_t* r0p = sa + (wRow + (mb << 4) + g) * ST + (t << 2);
            uint4 v0 = *(const uint4*)r0p;
            uint4 v1 = *(const uint4*)(r0p + (ST << 3));   // +8 rows
            #pragma unroll
            for (int nb = 0; nb < 4; nb++) {
                mma_bf16(acc[mb][nb], v0.x, v1.x, v0.y, v1.y, bv[nb].z, bv[nb].w); // ah*bl
                mma_bf16(acc[mb][nb], v0.z, v1.z, v0.w, v1.w, bv[nb].x, bv[nb].y); // al*bh
                mma_bf16(acc[mb][nb], v0.x, v1.x, v0.y, v1.y, bv[nb].x, bv[nb].y); // ah*bh
            }
        }

        if (more) {
            uint32_t* d = (cur ^ 1) ? dstBuf1 : dstBuf0;
            split_store8(d, woff, n0, n1);
        }
        __syncthreads();
    }

    // epilogue: each warp 32 rows x 32 cols
    const float inv_sqrt2 = 0.7071067811865475f;
    #pragma unroll
    for (int mb = 0; mb < 2; mb++) {
        int r0 = rowBase + wRow + (mb << 4) + g;
        #pragma unroll
        for (int half = 0; half < 2; half++) {
            int r = r0 + half * 8;
            if (r >= Rlim) continue;
            #pragma unroll
            for (int nb = 0; nb < 4; nb++) {
                int c = colBase + wCol + (nb << 3) + (t << 1);
                float vx = acc[mb][nb][half * 2 + 0];
                float vy = acc[mb][nb][half * 2 + 1];
                if (mode == 0) {
                    const float* rr = E2 + (size_t)r * ldc + c;
                    vx = vx * e1[c]     + rr[0];
                    vy = vy * e1[c + 1] + rr[1];
                } else if (mode == 1) {
                    vx += e1[c];
                    vy += e1[c + 1];
                    vx = 0.5f * vx * (1.0f + erff(vx * inv_sqrt2));
                    vy = 0.5f * vy * (1.0f + erff(vy * inv_sqrt2));
                } else {
                    const float* rr = E2 + (size_t)r * ldc + c;
                    vx += e1[c]     + rr[0];
                    vy += e1[c + 1] + rr[1];
                }
                *(float2*)(C + (size_t)r * ldc + c) = make_float2(vx, vy);
            }
        }
    }
}

// ============================================================
// Launch
// ============================================================
extern "C" void kernel_launch(void* const* d_in, const int* in_sizes, int n_in,
                              void* d_out, int out_size)
{
    (void)in_sizes; (void)n_in; (void)out_size;
    const float* savespace = (const float*)d_in[1];
    const float* Wqkv      = (const float*)d_in[2];
    const float* Wo        = (const float*)d_in[3];
    const float* ln1_g     = (const float*)d_in[4];
    const float* ln1_b     = (const float*)d_in[5];
    const float* ln2_g     = (const float*)d_in[6];
    const float* ln2_b     = (const float*)d_in[7];
    const float* fc1_w     = (const float*)d_in[8];
    const float* fc1_b     = (const float*)d_in[9];
    const float* fc2_w     = (const float*)d_in[10];
    const float* fc2_b     = (const float*)d_in[11];
    float* out = (float*)d_out;

    float *p_sln, *p_s2, *p_hln, *p_h1, *p_G, *p_Gp, *p_T, *p_ET, *p_ws;
    cudaGetSymbolAddress((void**)&p_sln, g_sln);
    cudaGetSymbolAddress((void**)&p_s2,  g_s2);
    cudaGetSymbolAddress((void**)&p_hln, g_hln);
    cudaGetSymbolAddress((void**)&p_h1,  g_h1);
    cudaGetSymbolAddress((void**)&p_G,   g_G);
    cudaGetSymbolAddress((void**)&p_Gp,  g_Gp);
    cudaGetSymbolAddress((void**)&p_T,   g_T);
    cudaGetSymbolAddress((void**)&p_ET,  g_ET);
    cudaGetSymbolAddress((void**)&p_ws,  g_wosum);

    const long SLAB = (long)J_ * M_;
    const long MM   = MM_;

    // 1) layernorm1
    ln_kernel<<<RTOT, 256>>>(savespace, ln1_g, ln1_b, p_sln);
    // 2) Gram partials + reduce
    gram_kernel<<<dim3(4, 4, NSLAB * NCH), 256>>>(p_sln, p_Gp);
    gram_reduce<<<dim3(64, NSLAB), 256>>>(p_Gp, p_G);
    // 3) Wo row sums
    rowsum_kernel<<<32, 256>>>(Wo, p_ws);
    // 4) T = G @ Wv_full^T per slab
    gemm64<<<dim3(4, 4, NSLAB), 256>>>(
        p_G, M_, MM,  Wqkv + 2 * H_ * DH_ * M_, M_, 0,  p_T, M_, MM, M_);
    // 5) finish ET per (head, slab)
    assemble2_kernel<<<dim3(H_, NSLAB), 256>>>(Wqkv, p_T, p_ET);
    // 6) s2 = wosum * (s_ln @ E) + savespace   [split-bf16, batched]
    bf16_gemm<<<dim3(9, 2, NSLAB), 512>>>(
        p_sln, M_, SLAB,  p_ET, M_, MM,  p_s2, M_, SLAB,
        M_, J_, 0, p_ws, savespace, SLAB);
    // 7) layernorm2
    ln_kernel<<<RTOT, 256>>>(p_s2, ln2_g, ln2_b, p_hln);
    // 8) h1 = gelu(hln @ fc1_w^T + b1)   [split-bf16]
    bf16_gemm<<<dim3(129, 8, 1), 512>>>(
        p_hln, M_, 0,  fc1_w, M_, 0,  p_h1, FF_, 0,
        M_, RTOT, 1, fc1_b, (const float*)0, 0);
    // 9) out = h1 @ fc2_w^T + b2 + s2    [split-bf16]
    bf16_gemm<<<dim3(129, 2, 1), 512>>>(
        p_h1, FF_, 0,  fc2_w, FF_, 0,  out, M_, 0,
        FF_, RTOT, 2, fc2_b, p_s2, 0);
}

// round 14
// speedup vs baseline: 1.1549x; 1.1549x over previous
#include <cuda_runtime.h>
#include <cuda_bf16.h>
#include <math.h>
#include <cstdint>

// Shapes (fixed by the problem)
#define B_    2
#define I_    8
#define J_    1025
#define M_    256
#define H_    8
#define DH_   32
#define NSLAB 16              // B_*I_
#define RTOT  (NSLAB * J_)    // 16400
#define FF_   1024            // 4*M
#define NCH   5               // gram J-chunks
#define MM_   (M_ * M_)

typedef unsigned long long u64;

// ---- scratch (static __device__ arrays; no runtime allocation) ----
__device__ float    g_sln[RTOT * M_];
__device__ float    g_s2 [RTOT * M_];
__device__ uint32_t g_hlnp[RTOT * M_];             // ln2 out, packed {hi|lo}
__device__ uint32_t g_h1p [(size_t)RTOT * FF_];    // gelu(fc1) out, packed
__device__ uint32_t g_w1p [FF_ * M_];              // fc1_w packed
__device__ uint32_t g_w2p [M_ * FF_];              // fc2_w packed
__device__ float    g_G  [NSLAB * MM_];
__device__ float    g_Gp [NCH * NSLAB * MM_];
__device__ float    g_T  [NSLAB * MM_];
__device__ float    g_ET [NSLAB * MM_];
__device__ float    g_wosum[M_];

// ---- f32x2 packed-FMA helpers ----
__device__ __forceinline__ u64 dup2(float x) {
    u64 r; asm("mov.b64 %0, {%1,%1};" : "=l"(r) : "f"(x)); return r;
}
__device__ __forceinline__ void fma2(u64& d, u64 a, u64 b) {
    asm("fma.rn.f32x2 %0, %1, %2, %0;" : "+l"(d) : "l"(a), "l"(b));
}
__device__ __forceinline__ float2 unpack2(u64 v) {
    float2 r; asm("mov.b64 {%0,%1}, %2;" : "=f"(r.x), "=f"(r.y) : "l"(v)); return r;
}

// ---- bf16 mma helper (m16n8k16, sm_80+) ----
__device__ __forceinline__ void mma_bf16(float* c,
    uint32_t a0, uint32_t a1, uint32_t a2, uint32_t a3,
    uint32_t b0, uint32_t b1)
{
    asm("mma.sync.aligned.m16n8k16.row.col.f32.bf16.bf16.f32 "
        "{%0,%1,%2,%3}, {%4,%5,%6,%7}, {%8,%9}, {%0,%1,%2,%3};"
        : "+f"(c[0]), "+f"(c[1]), "+f"(c[2]), "+f"(c[3])
        : "r"(a0), "r"(a1), "r"(a2), "r"(a3), "r"(b0), "r"(b1));
}
__device__ __forceinline__ uint32_t pack_lo2(float lo0, float lo1) {
    uint32_t r;
    asm("cvt.rn.bf16x2.f32 %0, %1, %2;" : "=r"(r) : "f"(lo1), "f"(lo0));
    return r;
}
// pack one fp32 into u32: hi bf16 (truncated) in top 16, lo bf16 in low 16
__device__ __forceinline__ uint32_t pack_split1(float x) {
    uint32_t u = __float_as_uint(x) & 0xFFFF0000u;
    float lo_f = x - __uint_as_float(u);
    __nv_bfloat16 lb = __float2bfloat16(lo_f);
    return u | (uint32_t)*(unsigned short*)&lb;
}

// ============================================================
// LayerNorm, warp-per-row (8 rows per 256-thr block), fp32 out
// ============================================================
__global__ void ln_kernel(const float* __restrict__ x,
                          const float* __restrict__ g,
                          const float* __restrict__ b,
                          float* __restrict__ out)
{
    int warp = threadIdx.x >> 5, lane = threadIdx.x & 31;
    int row = blockIdx.x * 8 + warp;
    const float* xr = x + (size_t)row * M_ + lane * 8;
    float4 v0 = *(const float4*)xr;
    float4 v1 = *(const float4*)(xr + 4);

    float s = v0.x + v0.y + v0.z + v0.w + v1.x + v1.y + v1.z + v1.w;
    #pragma unroll
    for (int o = 16; o > 0; o >>= 1) s += __shfl_xor_sync(0xffffffffu, s, o);
    float mean = s * (1.0f / M_);

    float d0 = v0.x - mean, d1 = v0.y - mean, d2 = v0.z - mean, d3 = v0.w - mean;
    float d4 = v1.x - mean, d5 = v1.y - mean, d6 = v1.z - mean, d7 = v1.w - mean;
    float q = d0*d0 + d1*d1 + d2*d2 + d3*d3 + d4*d4 + d5*d5 + d6*d6 + d7*d7;
    #pragma unroll
    for (int o = 16; o > 0; o >>= 1) q += __shfl_xor_sync(0xffffffffu, q, o);
    float rs = rsqrtf(q * (1.0f / M_) + 1e-5f);

    const float* gp = g + lane * 8;
    const float* bp = b + lane * 8;
    float4 g0 = *(const float4*)gp, g1 = *(const float4*)(gp + 4);
    float4 b0 = *(const float4*)bp, b1 = *(const float4*)(bp + 4);
    float4 o0, o1;
    o0.x = d0*rs*g0.x + b0.x; o0.y = d1*rs*g0.y + b0.y;
    o0.z = d2*rs*g0.z + b0.z; o0.w = d3*rs*g0.w + b0.w;
    o1.x = d4*rs*g1.x + b1.x; o1.y = d5*rs*g1.y + b1.y;
    o1.z = d6*rs*g1.z + b1.z; o1.w = d7*rs*g1.w + b1.w;
    float* op = out + (size_t)row * M_ + lane * 8;
    *(float4*)op = o0;
    *(float4*)(op + 4) = o1;
}

// ============================================================
// LayerNorm, warp-per-row, packed {hi|lo} out (for fc1 input)
// ============================================================
__global__ void ln_pack_kernel(const float* __restrict__ x,
                               const float* __restrict__ g,
                               const float* __restrict__ b,
                               uint32_t* __restrict__ out)
{
    int warp = threadIdx.x >> 5, lane = threadIdx.x & 31;
    int row = blockIdx.x * 8 + warp;
    const float* xr = x + (size_t)row * M_ + lane * 8;
    float4 v0 = *(const float4*)xr;
    float4 v1 = *(const float4*)(xr + 4);

    float s = v0.x + v0.y + v0.z + v0.w + v1.x + v1.y + v1.z + v1.w;
    #pragma unroll
    for (int o = 16; o > 0; o >>= 1) s += __shfl_xor_sync(0xffffffffu, s, o);
    float mean = s * (1.0f / M_);

    float d0 = v0.x - mean, d1 = v0.y - mean, d2 = v0.z - mean, d3 = v0.w - mean;
    float d4 = v1.x - mean, d5 = v1.y - mean, d6 = v1.z - mean, d7 = v1.w - mean;
    float q = d0*d0 + d1*d1 + d2*d2 + d3*d3 + d4*d4 + d5*d5 + d6*d6 + d7*d7;
    #pragma unroll
    for (int o = 16; o > 0; o >>= 1) q += __shfl_xor_sync(0xffffffffu, q, o);
    float rs = rsqrtf(q * (1.0f / M_) + 1e-5f);

    const float* gp = g + lane * 8;
    const float* bp = b + lane * 8;
    float4 g0 = *(const float4*)gp, g1 = *(const float4*)(gp + 4);
    float4 b0 = *(const float4*)bp, b1 = *(const float4*)(bp + 4);
    uint4 p0, p1;
    p0.x = pack_split1(d0*rs*g0.x + b0.x); p0.y = pack_split1(d1*rs*g0.y + b0.y);
    p0.z = pack_split1(d2*rs*g0.z + b0.z); p0.w = pack_split1(d3*rs*g0.w + b0.w);
    p1.x = pack_split1(d4*rs*g1.x + b1.x); p1.y = pack_split1(d5*rs*g1.y + b1.y);
    p1.z = pack_split1(d6*rs*g1.z + b1.z); p1.w = pack_split1(d7*rs*g1.w + b1.w);
    uint32_t* op = out + (size_t)row * M_ + lane * 8;
    *(uint4*)op = p0;
    *(uint4*)(op + 4) = p1;
}

// ============================================================
// Weight pack: fp32 -> u32 {hi|lo} (once per launch)
// ============================================================
__global__ void packw_kernel(const float* __restrict__ src,
                             uint32_t* __restrict__ dst, int n4)
{
    int i = blockIdx.x * 256 + threadIdx.x;
    if (i < n4) {
        float4 v = ((const float4*)src)[i];
        uint4 p;
        p.x = pack_split1(v.x); p.y = pack_split1(v.y);
        p.z = pack_split1(v.z); p.w = pack_split1(v.w);
        ((uint4*)dst)[i] = p;
    }
}

// ============================================================
// Wo row sums — one warp per row
// ============================================================
__global__ void rowsum_kernel(const float* __restrict__ Wo, float* __restrict__ ws)
{
    int warp = threadIdx.x >> 5, lane = threadIdx.x & 31;
    int n = blockIdx.x * 8 + warp;
    const float* row = Wo + (size_t)n * M_;
    float s = 0.f;
    #pragma unroll
    for (int m = lane; m < M_; m += 32) s += row[m];
    #pragma unroll
    for (int o = 16; o > 0; o >>= 1) s += __shfl_xor_sync(0xffffffffu, s, o);
    if (lane == 0) ws[n] = s;
}

// ============================================================
// Gram partials: J split in NCH chunks
// ============================================================
__global__ void __launch_bounds__(256) gram_kernel(const float* __restrict__ sln,
                                                   float* __restrict__ Gp)
{
    if (blockIdx.y < blockIdx.x) return;
    int zc = blockIdx.z;
    int slab = zc / NCH;
    int ch = zc - slab * NCH;
    const float* A = sln + (size_t)slab * J_ * M_;
    int p0 = blockIdx.x * 64, q0 = blockIdx.y * 64;

    int t0 = ch * 13, t1 = t0 + 13;

    __shared__ float As[2][16][64], Bs[2][16][64];
    int tid = threadIdx.x;
    int jj = tid >> 4;
    int cq = (tid & 15) << 2;
    int tx = tid & 15, ty = tid >> 4;

    float4 av, bv;
    {
        int j = t0 * 16 + jj;
        if (j < J_) {
            av = *(const float4*)(A + (size_t)j * M_ + p0 + cq);
            bv = *(const float4*)(A + (size_t)j * M_ + q0 + cq);
        } else { av = make_float4(0.f,0.f,0.f,0.f); bv = av; }
    }
    *(float4*)&As[0][jj][cq] = av;
    *(float4*)&Bs[0][jj][cq] = bv;
    __syncthreads();

    u64 acc[4][2] = {};
    for (int it = t0; it < t1; it++) {
        int cur = (it - t0) & 1;
        float4 nav, nbv;
        bool more = (it + 1 < t1);
        if (more) {
            int j = (it + 1) * 16 + jj;
            if (j < J_) {
                nav = *(const float4*)(A + (size_t)j * M_ + p0 + cq);
                nbv = *(const float4*)(A + (size_t)j * M_ + q0 + cq);
            } else { nav = make_float4(0.f,0.f,0.f,0.f); nbv = nav; }
        }
        #pragma unroll
        for (int k = 0; k < 16; k++) {
            float4 a = *(const float4*)&As[cur][k][ty << 2];
            ulonglong2 b = *(const ulonglong2*)&Bs[cur][k][tx << 2];
            u64 a2;
            a2 = dup2(a.x); fma2(acc[0][0], a2, b.x); fma2(acc[0][1], a2, b.y);
            a2 = dup2(a.y); fma2(acc[1][0], a2, b.x); fma2(acc[1][1], a2, b.y);
            a2 = dup2(a.z); fma2(acc[2][0], a2, b.x); fma2(acc[2][1], a2, b.y);
            a2 = dup2(a.w); fma2(acc[3][0], a2, b.x); fma2(acc[3][1], a2, b.y);
        }
        if (more) {
            *(float4*)&As[cur ^ 1][jj][cq] = nav;
            *(float4*)&Bs[cur ^ 1][jj][cq] = nbv;
        }
        __syncthreads();
    }
    float* Gs = Gp + (size_t)zc * MM_;
    #pragma unroll
    for (int i = 0; i < 4; i++) {
        int p = p0 + (ty << 2) + i;
        #pragma unroll
        for (int j2 = 0; j2 < 2; j2++) {
            float2 v = unpack2(acc[i][j2]);
            int q = q0 + (tx << 2) + j2 * 2;
            Gs[(size_t)p * M_ + q]     = v.x;
            Gs[(size_t)p * M_ + q + 1] = v.y;
            Gs[(size_t)q * M_ + p]       = v.x;
            Gs[(size_t)(q + 1) * M_ + p] = v.y;
        }
    }
}

// ============================================================
// Gram reduce
// ============================================================
__global__ void gram_reduce(const float* __restrict__ Gp, float* __restrict__ G)
{
    int slab = blockIdx.y;
    int idx = (blockIdx.x * 256 + threadIdx.x) * 4;
    const float* base = Gp + (size_t)slab * NCH * MM_ + idx;
    float4 s = *(const float4*)base;
    #pragma unroll
    for (int ch = 1; ch < NCH; ch++) {
        float4 v = *(const float4*)(base + (size_t)ch * MM_);
        s.x += v.x; s.y += v.y; s.z += v.z; s.w += v.w;
    }
    *(float4*)(G + (size_t)slab * MM_ + idx) = s;
}

// ============================================================
// 64x64 NT GEMM (T = G @ Wv^T)
// ============================================================
__global__ void __launch_bounds__(256) gemm64(
    const float* __restrict__ Ab, int lda, long aStride,
    const float* __restrict__ Bb, int ldb, long bStride,
    float* __restrict__ Cb, int ldc, long cStride, int K)
{
    int slab = blockIdx.z;
    const float* A = Ab + (size_t)slab * aStride;
    const float* B = Bb + (size_t)slab * bStride;
    float*       C = Cb + (size_t)slab * cStride;

    int rowBase = blockIdx.x * 64;
    int colBase = blockIdx.y * 64;

    __shared__ float As[16][64], Bs[16][64];
    int tid = threadIdx.x;
    int lm = tid >> 2;
    int lk = (tid & 3) << 2;
    int tx = tid & 15, ty = tid >> 4;

    u64 acc[4][2] = {};
    for (int k0 = 0; k0 < K; k0 += 16) {
        float4 av = *(const float4*)(A + (size_t)(rowBase + lm) * lda + k0 + lk);
        As[lk + 0][lm] = av.x; As[lk + 1][lm] = av.y;
        As[lk + 2][lm] = av.z; As[lk + 3][lm] = av.w;
        float4 bv = *(const float4*)(B + (size_t)(colBase + lm) * ldb + k0 + lk);
        Bs[lk + 0][lm] = bv.x; Bs[lk + 1][lm] = bv.y;
        Bs[lk + 2][lm] = bv.z; Bs[lk + 3][lm] = bv.w;
        __syncthreads();
        #pragma unroll
        for (int k = 0; k < 16; k++) {
            float4 a = *(const float4*)&As[k][ty << 2];
            ulonglong2 b = *(const ulonglong2*)&Bs[k][tx << 2];
            u64 a2;
            a2 = dup2(a.x); fma2(acc[0][0], a2, b.x); fma2(acc[0][1], a2, b.y);
            a2 = dup2(a.y); fma2(acc[1][0], a2, b.x); fma2(acc[1][1], a2, b.y);
            a2 = dup2(a.z); fma2(acc[2][0], a2, b.x); fma2(acc[2][1], a2, b.y);
            a2 = dup2(a.w); fma2(acc[3][0], a2, b.x); fma2(acc[3][1], a2, b.y);
        }
        __syncthreads();
    }
    #pragma unroll
    for (int i = 0; i < 4; i++) {
        int r = rowBase + (ty << 2) + i;
        #pragma unroll
        for (int j2 = 0; j2 < 2; j2++) {
            int c = colBase + (tx << 2) + j2 * 2;
            float2 v = unpack2(acc[i][j2]);
            *(float2*)(C + (size_t)r * ldc + c) = v;
        }
    }
}

// ============================================================
// Small per-(head,slab) finisher
// ============================================================
__global__ void __launch_bounds__(256) assemble2_kernel(const float* __restrict__ Wqkv,
                                                        const float* __restrict__ T,
                                                        float* __restrict__ ET)
{
    int h = blockIdx.x;
    int slab = blockIdx.y;
    const float* Ts = T + (size_t)slab * MM_;
    const float* Wq = Wqkv + (size_t)(0 * H_ + h) * DH_ * M_;
    const float* Wk = Wqkv + (size_t)(1 * H_ + h) * DH_ * M_;

    __shared__ float sT[256][33];
    __shared__ float ktv[32][33];
    int tid = threadIdx.x;

    {
        int m = tid >> 5, d = tid & 31;
        #pragma unroll
        for (int pass = 0; pass < 32; pass++) {
            int mm = pass * 8 + m;
            sT[mm][d] = Ts[(size_t)mm * M_ + h * 32 + d];
        }
    }
    __syncthreads();

    {
        int d  = tid & 31;
        int e0 = (tid >> 5) << 2;
        float acc4[4] = {0.f, 0.f, 0.f, 0.f};
        for (int m = 0; m < 256; m++) {
            float t = sT[m][d];
            #pragma unroll
            for (int ee = 0; ee < 4; ee++)
                acc4[ee] = fmaf(Wk[(size_t)(e0 + ee) * M_ + m], t, acc4[ee]);
        }
        #pragma unroll
        for (int ee = 0; ee < 4; ee++)
            ktv[e0 + ee][d] = acc4[ee];
    }
    __syncthreads();

    float acc3[32];
    #pragma unroll
    for (int d = 0; d < 32; d++) acc3[d] = 0.f;
    for (int e2 = 0; e2 < 32; e2++) {
        float w = Wq[(size_t)e2 * M_ + tid];
        #pragma unroll
        for (int d = 0; d < 32; d++) acc3[d] = fmaf(w, ktv[e2][d], acc3[d]);
    }
    const float scale = 0.17677669529663687f;
    float* ETs = ET + (size_t)slab * MM_;
    #pragma unroll
    for (int d = 0; d < 32; d++)
        ETs[(size_t)(h * 32 + d) * M_ + tid] = scale * acc3[d];
}

// ============================================================
// Runtime-split 3-product bf16 GEMM (R11 version; used for s2)
//   C = acc * e1[c] + e2[slab][r,c]
// ============================================================
#define ST 20
__device__ __forceinline__ void split_store8(uint32_t* rowp, int woff,
                                             float4 f0, float4 f1)
{
    uint32_t u0 = __float_as_uint(f0.x), u1 = __float_as_uint(f0.y);
    uint32_t u2 = __float_as_uint(f0.z), u3 = __float_as_uint(f0.w);
    uint32_t u4 = __float_as_uint(f1.x), u5 = __float_as_uint(f1.y);
    uint32_t u6 = __float_as_uint(f1.z), u7 = __float_as_uint(f1.w);
    uint32_t h01 = __byte_perm(u0, u1, 0x7632);
    uint32_t h23 = __byte_perm(u2, u3, 0x7632);
    uint32_t h45 = __byte_perm(u4, u5, 0x7632);
    uint32_t h67 = __byte_perm(u6, u7, 0x7632);
    uint32_t l01 = pack_lo2(f0.x - __uint_as_float(u0 & 0xFFFF0000u),
                            f0.y - __uint_as_float(u1 & 0xFFFF0000u));
    uint32_t l23 = pack_lo2(f0.z - __uint_as_float(u2 & 0xFFFF0000u),
                            f0.w - __uint_as_float(u3 & 0xFFFF0000u));
    uint32_t l45 = pack_lo2(f1.x - __uint_as_float(u4 & 0xFFFF0000u),
                            f1.y - __uint_as_float(u5 & 0xFFFF0000u));
    uint32_t l67 = pack_lo2(f1.z - __uint_as_float(u6 & 0xFFFF0000u),
                            f1.w - __uint_as_float(u7 & 0xFFFF0000u));
    *(uint4*)(rowp + woff)     = make_uint4(h01, h23, l01, l23);
    *(uint4*)(rowp + woff + 4) = make_uint4(h45, h67, l45, l67);
}

__global__ void __launch_bounds__(256) bf16_gemm_s2(
    const float* __restrict__ Ab, int lda, long aStr,
    const float* __restrict__ Bb, int ldb, long bStr,
    float* __restrict__ Cb, int ldc, long cStr,
    int K, int Rlim,
    const float* __restrict__ e1,
    const float* __restrict__ e2b, long e2Str)
{
    __shared__ uint32_t sA[2][128 * ST], sB[2][128 * ST];
    int tid = threadIdx.x;
    int slab = blockIdx.z;
    const float* A = Ab + (size_t)slab * aStr;
    const float* B = Bb + (size_t)slab * bStr;
    float*       C = Cb + (size_t)slab * cStr;
    const float* E2 = e2b + (size_t)slab * e2Str;

    int rowBase = blockIdx.x * 128, colBase = blockIdx.y * 128;

    int ldRow = tid >> 1;
    int ldK   = (tid & 1) << 3;
    int woff  = (tid & 1) << 3;
    const float* Arow = A + (size_t)(rowBase + ldRow) * lda + ldK;
    const float* Brow = B + (size_t)(colBase + ldRow) * ldb + ldK;
    bool aValid = (rowBase + ldRow) < Rlim;

    int lane = tid & 31, warp = tid >> 5;
    int wRow = (warp >> 2) << 6;
    int wCol = (warp & 3) << 5;
    int g = lane >> 2, t = lane & 3;

    const int NT = K >> 4;
    const float4 z4 = make_float4(0.f, 0.f, 0.f, 0.f);

    {
        float4 a0 = aValid ? *(const float4*)Arow : z4;
        float4 a1 = aValid ? *(const float4*)(Arow + 4) : z4;
        split_store8(&sA[0][ldRow * ST], woff, a0, a1);
        float4 b0 = *(const float4*)Brow;
        float4 b1 = *(const float4*)(Brow + 4);
        split_store8(&sB[0][ldRow * ST], woff, b0, b1);
    }
    __syncthreads();

    float acc[4][4][4];
    #pragma unroll
    for (int i = 0; i < 4; i++)
        #pragma unroll
        for (int j = 0; j < 4; j++)
            #pragma unroll
            for (int q = 0; q < 4; q++) acc[i][j][q] = 0.f;

    for (int it = 0; it < NT; it++) {
        int cur = it & 1;
        bool more = (it + 1 < NT);
        float4 na0, na1, nb0, nb1;
        if (more) {
            int k0 = (it + 1) << 4;
            na0 = aValid ? *(const float4*)(Arow + k0) : z4;
            na1 = aValid ? *(const float4*)(Arow + k0 + 4) : z4;
            nb0 = *(const float4*)(Brow + k0);
            nb1 = *(const float4*)(Brow + k0 + 4);
        }

        const uint32_t* sa = sA[cur];
        const uint32_t* sb = sB[cur];

        uint4 bv[4];
        #pragma unroll
        for (int nb = 0; nb < 4; nb++)
            bv[nb] = *(const uint4*)(sb + (wCol + (nb << 3) + g) * ST + (t << 2));

        #pragma unroll
        for (int mb = 0; mb < 4; mb++) {
            const uint32_t* r0p = sa + (wRow + (mb << 4) + g) * ST + (t << 2);
            uint4 v0 = *(const uint4*)r0p;
            uint4 v1 = *(const uint4*)(r0p + (ST << 3));
            #pragma unroll
            for (int nb = 0; nb < 4; nb++) {
                mma_bf16(acc[mb][nb], v0.x, v1.x, v0.y, v1.y, bv[nb].z, bv[nb].w);
                mma_bf16(acc[mb][nb], v0.z, v1.z, v0.w, v1.w, bv[nb].x, bv[nb].y);
                mma_bf16(acc[mb][nb], v0.x, v1.x, v0.y, v1.y, bv[nb].x, bv[nb].y);
            }
        }

        if (more) {
            int nxt = cur ^ 1;
            split_store8(&sA[nxt][ldRow * ST], woff, na0, na1);
            split_store8(&sB[nxt][ldRow * ST], woff, nb0, nb1);
        }
        __syncthreads();
    }

    #pragma unroll
    for (int mb = 0; mb < 4; mb++) {
        int r0 = rowBase + wRow + (mb << 4) + g;
        #pragma unroll
        for (int half = 0; half < 2; half++) {
            int r = r0 + half * 8;
            if (r >= Rlim) continue;
            #pragma unroll
            for (int nb = 0; nb < 4; nb++) {
                int c = colBase + wCol + (nb << 3) + (t << 1);
                float vx = acc[mb][nb][half * 2 + 0];
                float vy = acc[mb][nb][half * 2 + 1];
                const float* rr = E2 + (size_t)r * ldc + c;
                vx = vx * e1[c]     + rr[0];
                vy = vy * e1[c + 1] + rr[1];
                *(float2*)(C + (size_t)r * ldc + c) = make_float2(vx, vy);
            }
        }
    }
}

// ============================================================
// PRE-SPLIT 3-product bf16 GEMM (fc1/fc2): inputs are u32
// packed {hi|lo}; loader is LDG.128 + PRMT pair-grouping only.
//   mode 1: Cp[r,c] = pack(gelu(acc + bias[c]))
//   mode 2: Cf[r,c] = acc + bias[c] + resid[r,c]
// ============================================================
__device__ __forceinline__ void prmt_store8(uint32_t* rowp, int woff,
                                            uint4 e0, uint4 e1)
{
    // pairs: (e0.x,e0.y) (e0.z,e0.w) (e1.x,e1.y) (e1.z,e1.w)
    uint32_t h01 = __byte_perm(e0.x, e0.y, 0x7632);
    uint32_t l01 = __byte_perm(e0.x, e0.y, 0x5410);
    uint32_t h23 = __byte_perm(e0.z, e0.w, 0x7632);
    uint32_t l23 = __byte_perm(e0.z, e0.w, 0x5410);
    uint32_t h45 = __byte_perm(e1.x, e1.y, 0x7632);
    uint32_t l45 = __byte_perm(e1.x, e1.y, 0x5410);
    uint32_t h67 = __byte_perm(e1.z, e1.w, 0x7632);
    uint32_t l67 = __byte_perm(e1.z, e1.w, 0x5410);
    *(uint4*)(rowp + woff)     = make_uint4(h01, h23, l01, l23);
    *(uint4*)(rowp + woff + 4) = make_uint4(h45, h67, l45, l67);
}

__global__ void __launch_bounds__(256) bf16_gemm_ps(
    const uint32_t* __restrict__ A, int lda,
    const uint32_t* __restrict__ B, int ldb,
    int K, int Rlim, int mode, int ldc,
    const float* __restrict__ bias,
    const float* __restrict__ resid,
    float* __restrict__ Cf,
    uint32_t* __restrict__ Cp)
{
    __shared__ uint32_t sA[2][128 * ST], sB[2][128 * ST];
    int tid = threadIdx.x;
    int rowBase = blockIdx.x * 128, colBase = blockIdx.y * 128;

    int ldRow = tid >> 1;
    int ldK   = (tid & 1) << 3;
    int woff  = (tid & 1) << 3;
    const uint32_t* Arow = A + (size_t)(rowBase + ldRow) * lda + ldK;
    const uint32_t* Brow = B + (size_t)(colBase + ldRow) * ldb + ldK;
    bool aValid = (rowBase + ldRow) < Rlim;

    int lane = tid & 31, warp = tid >> 5;
    int wRow = (warp >> 2) << 6;
    int wCol = (warp & 3) << 5;
    int g = lane >> 2, t = lane & 3;

    const int NT = K >> 4;
    const uint4 z4 = make_uint4(0u, 0u, 0u, 0u);

    {
        uint4 a0 = aValid ? *(const uint4*)Arow : z4;
        uint4 a1 = aValid ? *(const uint4*)(Arow + 4) : z4;
        prmt_store8(&sA[0][ldRow * ST], woff, a0, a1);
        uint4 b0 = *(const uint4*)Brow;
        uint4 b1 = *(const uint4*)(Brow + 4);
        prmt_store8(&sB[0][ldRow * ST], woff, b0, b1);
    }
    __syncthreads();

    float acc[4][4][4];
    #pragma unroll
    for (int i = 0; i < 4; i++)
        #pragma unroll
        for (int j = 0; j < 4; j++)
            #pragma unroll
            for (int q = 0; q < 4; q++) acc[i][j][q] = 0.f;

    for (int it = 0; it < NT; it++) {
        int cur = it & 1;
        bool more = (it + 1 < NT);
        uint4 na0, na1, nb0, nb1;
        if (more) {
            int k0 = (it + 1) << 4;
            na0 = aValid ? *(const uint4*)(Arow + k0) : z4;
            na1 = aValid ? *(const uint4*)(Arow + k0 + 4) : z4;
            nb0 = *(const uint4*)(Brow + k0);
            nb1 = *(const uint4*)(Brow + k0 + 4);
        }

        const uint32_t* sa = sA[cur];
        const uint32_t* sb = sB[cur];

        uint4 bv[4];
        #pragma unroll
        for (int nb = 0; nb < 4; nb++)
            bv[nb] = *(const uint4*)(sb + (wCol + (nb << 3) + g) * ST + (t << 2));

        #pragma unroll
        for (int mb = 0; mb < 4; mb++) {
            const uint32_t* r0p = sa + (wRow + (mb << 4) + g) * ST + (t << 2);
            uint4 v0 = *(const uint4*)r0p;
            uint4 v1 = *(const uint4*)(r0p + (ST << 3));
            #pragma unroll
            for (int nb = 0; nb < 4; nb++) {
                mma_bf16(acc[mb][nb], v0.x, v1.x, v0.y, v1.y, bv[nb].z, bv[nb].w); // ah*bl
                mma_bf16(acc[mb][nb], v0.z, v1.z, v0.w, v1.w, bv[nb].x, bv[nb].y); // al*bh
                mma_bf16(acc[mb][nb], v0.x, v1.x, v0.y, v1.y, bv[nb].x, bv[nb].y); // ah*bh
            }
        }

        if (more) {
            int nxt = cur ^ 1;
            prmt_store8(&sA[nxt][ldRow * ST], woff, na0, na1);
            prmt_store8(&sB[nxt][ldRow * ST], woff, nb0, nb1);
        }
        __syncthreads();
    }

    const float inv_sqrt2 = 0.7071067811865475f;
    #pragma unroll
    for (int mb = 0; mb < 4; mb++) {
        int r0 = rowBase + wRow + (mb << 4) + g;
        #pragma unroll
        for (int half = 0; half < 2; half++) {
            int r = r0 + half * 8;
            if (r >= Rlim) continue;
            #pragma unroll
            for (int nb = 0; nb < 4; nb++) {
                int c = colBase + wCol + (nb << 3) + (t << 1);
                float vx = acc[mb][nb][half * 2 + 0];
                float vy = acc[mb][nb][half * 2 + 1];
                if (mode == 1) {
                    vx += bias[c];
                    vy += bias[c + 1];
                    vx = 0.5f * vx * (1.0f + erff(vx * inv_sqrt2));
                    vy = 0.5f * vy * (1.0f + erff(vy * inv_sqrt2));
                    uint32_t px = pack_split1(vx);
                    uint32_t py = pack_split1(vy);
                    *(uint2*)(Cp + (size_t)r * ldc + c) = make_uint2(px, py);
                } else {
                    const float* rr = resid + (size_t)r * ldc + c;
                    vx += bias[c]     + rr[0];
                    vy += bias[c + 1] + rr[1];
                    *(float2*)(Cf + (size_t)r * ldc + c) = make_float2(vx, vy);
                }
            }
        }
    }
}

// ============================================================
// Launch
// ============================================================
extern "C" void kernel_launch(void* const* d_in, const int* in_sizes, int n_in,
                              void* d_out, int out_size)
{
    (void)in_sizes; (void)n_in; (void)out_size;
    const float* savespace = (const float*)d_in[1];
    const float* Wqkv      = (const float*)d_in[2];
    const float* Wo        = (const float*)d_in[3];
    const float* ln1_g     = (const float*)d_in[4];
    const float* ln1_b     = (const float*)d_in[5];
    const float* ln2_g     = (const float*)d_in[6];
    const float* ln2_b     = (const float*)d_in[7];
    const float* fc1_w     = (const float*)d_in[8];
    const float* fc1_b     = (const float*)d_in[9];
    const float* fc2_w     = (const float*)d_in[10];
    const float* fc2_b     = (const float*)d_in[11];
    float* out = (float*)d_out;

    float *p_sln, *p_s2, *p_G, *p_Gp, *p_T, *p_ET, *p_ws;
    uint32_t *p_hlnp, *p_h1p, *p_w1p, *p_w2p;
    cudaGetSymbolAddress((void**)&p_sln, g_sln);
    cudaGetSymbolAddress((void**)&p_s2,  g_s2);
    cudaGetSymbolAddress((void**)&p_G,   g_G);
    cudaGetSymbolAddress((void**)&p_Gp,  g_Gp);
    cudaGetSymbolAddress((void**)&p_T,   g_T);
    cudaGetSymbolAddress((void**)&p_ET,  g_ET);
    cudaGetSymbolAddress((void**)&p_ws,  g_wosum);
    cudaGetSymbolAddress((void**)&p_hlnp, g_hlnp);
    cudaGetSymbolAddress((void**)&p_h1p,  g_h1p);
    cudaGetSymbolAddress((void**)&p_w1p,  g_w1p);
    cudaGetSymbolAddress((void**)&p_w2p,  g_w2p);

    const long SLAB = (long)J_ * M_;
    const long MM   = MM_;

    // 1) layernorm1 (warp-per-row)
    ln_kernel<<<RTOT / 8, 256>>>(savespace, ln1_g, ln1_b, p_sln);
    // 2) pack weights (once per launch; independent of step 1)
    packw_kernel<<<(FF_ * M_ / 4 + 255) / 256, 256>>>(fc1_w, p_w1p, FF_ * M_ / 4);
    packw_kernel<<<(M_ * FF_ / 4 + 255) / 256, 256>>>(fc2_w, p_w2p, M_ * FF_ / 4);
    // 3) Gram partials + reduce
    gram_kernel<<<dim3(4, 4, NSLAB * NCH), 256>>>(p_sln, p_Gp);
    gram_reduce<<<dim3(64, NSLAB), 256>>>(p_Gp, p_G);
    // 4) Wo row sums
    rowsum_kernel<<<32, 256>>>(Wo, p_ws);
    // 5) T = G @ Wv_full^T per slab
    gemm64<<<dim3(4, 4, NSLAB), 256>>>(
        p_G, M_, MM,  Wqkv + 2 * H_ * DH_ * M_, M_, 0,  p_T, M_, MM, M_);
    // 6) finish ET per (head, slab)
    assemble2_kernel<<<dim3(H_, NSLAB), 256>>>(Wqkv, p_T, p_ET);
    // 7) s2 = wosum * (s_ln @ E) + savespace   [runtime-split bf16]
    bf16_gemm_s2<<<dim3(9, 2, NSLAB), 256>>>(
        p_sln, M_, SLAB,  p_ET, M_, MM,  p_s2, M_, SLAB,
        M_, J_, p_ws, savespace, SLAB);
    // 8) layernorm2 -> packed {hi|lo}
    ln_pack_kernel<<<RTOT / 8, 256>>>(p_s2, ln2_g, ln2_b, p_hlnp);
    // 9) h1p = pack(gelu(hln @ fc1_w^T + b1))   [pre-split bf16]
    bf16_gemm_ps<<<dim3(129, 8), 256>>>(
        p_hlnp, M_, p_w1p, M_,
        M_, RTOT, 1, FF_, fc1_b, (const float*)0, (float*)0, p_h1p);
    // 10) out = h1 @ fc2_w^T + b2 + s2          [pre-split bf16]
    bf16_gemm_ps<<<dim3(129, 2), 256>>>(
        p_h1p, FF_, p_w2p, FF_,
        FF_, RTOT, 2, M_, fc2_b, p_s2, out, (uint32_t*)0);
}

// round 15
// speedup vs baseline: 1.6731x; 1.4486x over previous
#include <cuda_runtime.h>
#include <cuda_bf16.h>
#include <math.h>
#include <cstdint>

// Shapes (fixed by the problem)
#define B_    2
#define I_    8
#define J_    1025
#define M_    256
#define H_    8
#define DH_   32
#define NSLAB 16              // B_*I_
#define RTOT  (NSLAB * J_)    // 16400
#define FF_   1024            // 4*M
#define NCH   5               // gram J-chunks
#define MM_   (M_ * M_)

typedef unsigned long long u64;

// ---- scratch (static __device__ arrays; no runtime allocation) ----
__device__ float    g_sln[RTOT * M_];
__device__ float    g_s2 [RTOT * M_];
__device__ uint32_t g_hlnb[RTOT * M_ / 2];          // ln2 out, bf16x2
__device__ uint32_t g_h1b [(size_t)RTOT * FF_ / 2]; // gelu(fc1) out, bf16x2
__device__ uint32_t g_w1b [FF_ * M_ / 2];           // fc1_w bf16x2
__device__ uint32_t g_w2b [M_ * FF_ / 2];           // fc2_w bf16x2
__device__ float    g_G  [NSLAB * MM_];
__device__ float    g_Gp [NCH * NSLAB * MM_];
__device__ float    g_T  [NSLAB * MM_];
__device__ float    g_ET [NSLAB * MM_];
__device__ float    g_wosum[M_];

// ---- f32x2 packed-FMA helpers ----
__device__ __forceinline__ u64 dup2(float x) {
    u64 r; asm("mov.b64 %0, {%1,%1};" : "=l"(r) : "f"(x)); return r;
}
__device__ __forceinline__ void fma2(u64& d, u64 a, u64 b) {
    asm("fma.rn.f32x2 %0, %1, %2, %0;" : "+l"(d) : "l"(a), "l"(b));
}
__device__ __forceinline__ float2 unpack2(u64 v) {
    float2 r; asm("mov.b64 {%0,%1}, %2;" : "=f"(r.x), "=f"(r.y) : "l"(v)); return r;
}

// ---- bf16 mma helper (m16n8k16, sm_80+) ----
__device__ __forceinline__ void mma_bf16(float* c,
    uint32_t a0, uint32_t a1, uint32_t a2, uint32_t a3,
    uint32_t b0, uint32_t b1)
{
    asm("mma.sync.aligned.m16n8k16.row.col.f32.bf16.bf16.f32 "
        "{%0,%1,%2,%3}, {%4,%5,%6,%7}, {%8,%9}, {%0,%1,%2,%3};"
        : "+f"(c[0]), "+f"(c[1]), "+f"(c[2]), "+f"(c[3])
        : "r"(a0), "r"(a1), "r"(a2), "r"(a3), "r"(b0), "r"(b1));
}
// pack two floats to bf16x2 (x in low half)
__device__ __forceinline__ uint32_t pack_bf2(float x, float y) {
    uint32_t r;
    asm("cvt.rn.bf16x2.f32 %0, %1, %2;" : "=r"(r) : "f"(y), "f"(x));
    return r;
}

// ============================================================
// LayerNorm, warp-per-row (8 rows per 256-thr block), fp32 out
// ============================================================
__global__ void ln_kernel(const float* __restrict__ x,
                          const float* __restrict__ g,
                          const float* __restrict__ b,
                          float* __restrict__ out)
{
    int warp = threadIdx.x >> 5, lane = threadIdx.x & 31;
    int row = blockIdx.x * 8 + warp;
    const float* xr = x + (size_t)row * M_ + lane * 8;
    float4 v0 = *(const float4*)xr;
    float4 v1 = *(const float4*)(xr + 4);

    float s = v0.x + v0.y + v0.z + v0.w + v1.x + v1.y + v1.z + v1.w;
    #pragma unroll
    for (int o = 16; o > 0; o >>= 1) s += __shfl_xor_sync(0xffffffffu, s, o);
    float mean = s * (1.0f / M_);

    float d0 = v0.x - mean, d1 = v0.y - mean, d2 = v0.z - mean, d3 = v0.w - mean;
    float d4 = v1.x - mean, d5 = v1.y - mean, d6 = v1.z - mean, d7 = v1.w - mean;
    float q = d0*d0 + d1*d1 + d2*d2 + d3*d3 + d4*d4 + d5*d5 + d6*d6 + d7*d7;
    #pragma unroll
    for (int o = 16; o > 0; o >>= 1) q += __shfl_xor_sync(0xffffffffu, q, o);
    float rs = rsqrtf(q * (1.0f / M_) + 1e-5f);

    const float* gp = g + lane * 8;
    const float* bp = b + lane * 8;
    float4 g0 = *(const float4*)gp, g1 = *(const float4*)(gp + 4);
    float4 b0 = *(const float4*)bp, b1 = *(const float4*)(bp + 4);
    float4 o0, o1;
    o0.x = d0*rs*g0.x + b0.x; o0.y = d1*rs*g0.y + b0.y;
    o0.z = d2*rs*g0.z + b0.z; o0.w = d3*rs*g0.w + b0.w;
    o1.x = d4*rs*g1.x + b1.x; o1.y = d5*rs*g1.y + b1.y;
    o1.z = d6*rs*g1.z + b1.z; o1.w = d7*rs*g1.w + b1.w;
    float* op = out + (size_t)row * M_ + lane * 8;
    *(float4*)op = o0;
    *(float4*)(op + 4) = o1;
}

// ============================================================
// LayerNorm, warp-per-row, bf16x2 out (feeds fc1 only)
// ============================================================
__global__ void ln_bf16_kernel(const float* __restrict__ x,
                               const float* __restrict__ g,
                               const float* __restrict__ b,
                               uint32_t* __restrict__ out)
{
    int warp = threadIdx.x >> 5, lane = threadIdx.x & 31;
    int row = blockIdx.x * 8 + warp;
    const float* xr = x + (size_t)row * M_ + lane * 8;
    float4 v0 = *(const float4*)xr;
    float4 v1 = *(const float4*)(xr + 4);

    float s = v0.x + v0.y + v0.z + v0.w + v1.x + v1.y + v1.z + v1.w;
    #pragma unroll
    for (int o = 16; o > 0; o >>= 1) s += __shfl_xor_sync(0xffffffffu, s, o);
    float mean = s * (1.0f / M_);

    float d0 = v0.x - mean, d1 = v0.y - mean, d2 = v0.z - mean, d3 = v0.w - mean;
    float d4 = v1.x - mean, d5 = v1.y - mean, d6 = v1.z - mean, d7 = v1.w - mean;
    float q = d0*d0 + d1*d1 + d2*d2 + d3*d3 + d4*d4 + d5*d5 + d6*d6 + d7*d7;
    #pragma unroll
    for (int o = 16; o > 0; o >>= 1) q += __shfl_xor_sync(0xffffffffu, q, o);
    float rs = rsqrtf(q * (1.0f / M_) + 1e-5f);

    const float* gp = g + lane * 8;
    const float* bp = b + lane * 8;
    float4 g0 = *(const float4*)gp, g1 = *(const float4*)(gp + 4);
    float4 b0 = *(const float4*)bp, b1 = *(const float4*)(bp + 4);
    uint4 p;
    p.x = pack_bf2(d0*rs*g0.x + b0.x, d1*rs*g0.y + b0.y);
    p.y = pack_bf2(d2*rs*g0.z + b0.z, d3*rs*g0.w + b0.w);
    p.z = pack_bf2(d4*rs*g1.x + b1.x, d5*rs*g1.y + b1.y);
    p.w = pack_bf2(d6*rs*g1.z + b1.z, d7*rs*g1.w + b1.w);
    *(uint4*)(out + (size_t)row * (M_ / 2) + lane * 4) = p;
}

// ============================================================
// Weight pack: fp32 -> bf16x2
// ============================================================
__global__ void packw_kernel(const float* __restrict__ src,
                             uint32_t* __restrict__ dst, int n4)
{
    int i = blockIdx.x * 256 + threadIdx.x;
    if (i < n4) {
        float4 v = ((const float4*)src)[i];
        uint2 p;
        p.x = pack_bf2(v.x, v.y);
        p.y = pack_bf2(v.z, v.w);
        ((uint2*)dst)[i] = p;
    }
}

// ============================================================
// Wo row sums — one warp per row
// ============================================================
__global__ void rowsum_kernel(const float* __restrict__ Wo, float* __restrict__ ws)
{
    int warp = threadIdx.x >> 5, lane = threadIdx.x & 31;
    int n = blockIdx.x * 8 + warp;
    const float* row = Wo + (size_t)n * M_;
    float s = 0.f;
    #pragma unroll
    for (int m = lane; m < M_; m += 32) s += row[m];
    #pragma unroll
    for (int o = 16; o > 0; o >>= 1) s += __shfl_xor_sync(0xffffffffu, s, o);
    if (lane == 0) ws[n] = s;
}

// ============================================================
// Gram partials: J split in NCH chunks (fp32 FFMA2 — precision path)
// ============================================================
__global__ void __launch_bounds__(256) gram_kernel(const float* __restrict__ sln,
                                                   float* __restrict__ Gp)
{
    if (blockIdx.y < blockIdx.x) return;
    int zc = blockIdx.z;
    int slab = zc / NCH;
    int ch = zc - slab * NCH;
    const float* A = sln + (size_t)slab * J_ * M_;
    int p0 = blockIdx.x * 64, q0 = blockIdx.y * 64;

    int t0 = ch * 13, t1 = t0 + 13;

    __shared__ float As[2][16][64], Bs[2][16][64];
    int tid = threadIdx.x;
    int jj = tid >> 4;
    int cq = (tid & 15) << 2;
    int tx = tid & 15, ty = tid >> 4;

    float4 av, bv;
    {
        int j = t0 * 16 + jj;
        if (j < J_) {
            av = *(const float4*)(A + (size_t)j * M_ + p0 + cq);
            bv = *(const float4*)(A + (size_t)j * M_ + q0 + cq);
        } else { av = make_float4(0.f,0.f,0.f,0.f); bv = av; }
    }
    *(float4*)&As[0][jj][cq] = av;
    *(float4*)&Bs[0][jj][cq] = bv;
    __syncthreads();

    u64 acc[4][2] = {};
    for (int it = t0; it < t1; it++) {
        int cur = (it - t0) & 1;
        float4 nav, nbv;
        bool more = (it + 1 < t1);
        if (more) {
            int j = (it + 1) * 16 + jj;
            if (j < J_) {
                nav = *(const float4*)(A + (size_t)j * M_ + p0 + cq);
                nbv = *(const float4*)(A + (size_t)j * M_ + q0 + cq);
            } else { nav = make_float4(0.f,0.f,0.f,0.f); nbv = nav; }
        }
        #pragma unroll
        for (int k = 0; k < 16; k++) {
            float4 a = *(const float4*)&As[cur][k][ty << 2];
            ulonglong2 b = *(const ulonglong2*)&Bs[cur][k][tx << 2];
            u64 a2;
            a2 = dup2(a.x); fma2(acc[0][0], a2, b.x); fma2(acc[0][1], a2, b.y);
            a2 = dup2(a.y); fma2(acc[1][0], a2, b.x); fma2(acc[1][1], a2, b.y);
            a2 = dup2(a.z); fma2(acc[2][0], a2, b.x); fma2(acc[2][1], a2, b.y);
            a2 = dup2(a.w); fma2(acc[3][0], a2, b.x); fma2(acc[3][1], a2, b.y);
        }
        if (more) {
            *(float4*)&As[cur ^ 1][jj][cq] = nav;
            *(float4*)&Bs[cur ^ 1][jj][cq] = nbv;
        }
        __syncthreads();
    }
    float* Gs = Gp + (size_t)zc * MM_;
    #pragma unroll
    for (int i = 0; i < 4; i++) {
        int p = p0 + (ty << 2) + i;
        #pragma unroll
        for (int j2 = 0; j2 < 2; j2++) {
            float2 v = unpack2(acc[i][j2]);
            int q = q0 + (tx << 2) + j2 * 2;
            Gs[(size_t)p * M_ + q]     = v.x;
            Gs[(size_t)p * M_ + q + 1] = v.y;
            Gs[(size_t)q * M_ + p]       = v.x;
            Gs[(size_t)(q + 1) * M_ + p] = v.y;
        }
    }
}

// ============================================================
// Gram reduce
// ============================================================
__global__ void gram_reduce(const float* __restrict__ Gp, float* __restrict__ G)
{
    int slab = blockIdx.y;
    int idx = (blockIdx.x * 256 + threadIdx.x) * 4;
    const float* base = Gp + (size_t)slab * NCH * MM_ + idx;
    float4 s = *(const float4*)base;
    #pragma unroll
    for (int ch = 1; ch < NCH; ch++) {
        float4 v = *(const float4*)(base + (size_t)ch * MM_);
        s.x += v.x; s.y += v.y; s.z += v.z; s.w += v.w;
    }
    *(float4*)(G + (size_t)slab * MM_ + idx) = s;
}

// ============================================================
// 64x64 NT GEMM (T = G @ Wv^T)
// ============================================================
__global__ void __launch_bounds__(256) gemm64(
    const float* __restrict__ Ab, int lda, long aStride,
    const float* __restrict__ Bb, int ldb, long bStride,
    float* __restrict__ Cb, int ldc, long cStride, int K)
{
    int slab = blockIdx.z;
    const float* A = Ab + (size_t)slab * aStride;
    const float* B = Bb + (size_t)slab * bStride;
    float*       C = Cb + (size_t)slab * cStride;

    int rowBase = blockIdx.x * 64;
    int colBase = blockIdx.y * 64;

    __shared__ float As[16][64], Bs[16][64];
    int tid = threadIdx.x;
    int lm = tid >> 2;
    int lk = (tid & 3) << 2;
    int tx = tid & 15, ty = tid >> 4;

    u64 acc[4][2] = {};
    for (int k0 = 0; k0 < K; k0 += 16) {
        float4 av = *(const float4*)(A + (size_t)(rowBase + lm) * lda + k0 + lk);
        As[lk + 0][lm] = av.x; As[lk + 1][lm] = av.y;
        As[lk + 2][lm] = av.z; As[lk + 3][lm] = av.w;
        float4 bv = *(const float4*)(B + (size_t)(colBase + lm) * ldb + k0 + lk);
        Bs[lk + 0][lm] = bv.x; Bs[lk + 1][lm] = bv.y;
        Bs[lk + 2][lm] = bv.z; Bs[lk + 3][lm] = bv.w;
        __syncthreads();
        #pragma unroll
        for (int k = 0; k < 16; k++) {
            float4 a = *(const float4*)&As[k][ty << 2];
            ulonglong2 b = *(const ulonglong2*)&Bs[k][tx << 2];
            u64 a2;
            a2 = dup2(a.x); fma2(acc[0][0], a2, b.x); fma2(acc[0][1], a2, b.y);
            a2 = dup2(a.y); fma2(acc[1][0], a2, b.x); fma2(acc[1][1], a2, b.y);
            a2 = dup2(a.z); fma2(acc[2][0], a2, b.x); fma2(acc[2][1], a2, b.y);
            a2 = dup2(a.w); fma2(acc[3][0], a2, b.x); fma2(acc[3][1], a2, b.y);
        }
        __syncthreads();
    }
    #pragma unroll
    for (int i = 0; i < 4; i++) {
        int r = rowBase + (ty << 2) + i;
        #pragma unroll
        for (int j2 = 0; j2 < 2; j2++) {
            int c = colBase + (tx << 2) + j2 * 2;
            float2 v = unpack2(acc[i][j2]);
            *(float2*)(C + (size_t)r * ldc + c) = v;
        }
    }
}

// ============================================================
// Small per-(head,slab) finisher
// ============================================================
__global__ void __launch_bounds__(256) assemble2_kernel(const float* __restrict__ Wqkv,
                                                        const float* __restrict__ T,
                                                        float* __restrict__ ET)
{
    int h = blockIdx.x;
    int slab = blockIdx.y;
    const float* Ts = T + (size_t)slab * MM_;
    const float* Wq = Wqkv + (size_t)(0 * H_ + h) * DH_ * M_;
    const float* Wk = Wqkv + (size_t)(1 * H_ + h) * DH_ * M_;

    __shared__ float sT[256][33];
    __shared__ float ktv[32][33];
    int tid = threadIdx.x;

    {
        int m = tid >> 5, d = tid & 31;
        #pragma unroll
        for (int pass = 0; pass < 32; pass++) {
            int mm = pass * 8 + m;
            sT[mm][d] = Ts[(size_t)mm * M_ + h * 32 + d];
        }
    }
    __syncthreads();

    {
        int d  = tid & 31;
        int e0 = (tid >> 5) << 2;
        float acc4[4] = {0.f, 0.f, 0.f, 0.f};
        for (int m = 0; m < 256; m++) {
            float t = sT[m][d];
            #pragma unroll
            for (int ee = 0; ee < 4; ee++)
                acc4[ee] = fmaf(Wk[(size_t)(e0 + ee) * M_ + m], t, acc4[ee]);
        }
        #pragma unroll
        for (int ee = 0; ee < 4; ee++)
            ktv[e0 + ee][d] = acc4[ee];
    }
    __syncthreads();

    float acc3[32];
    #pragma unroll
    for (int d = 0; d < 32; d++) acc3[d] = 0.f;
    for (int e2 = 0; e2 < 32; e2++) {
        float w = Wq[(size_t)e2 * M_ + tid];
        #pragma unroll
        for (int d = 0; d < 32; d++) acc3[d] = fmaf(w, ktv[e2][d], acc3[d]);
    }
    const float scale = 0.17677669529663687f;
    float* ETs = ET + (size_t)slab * MM_;
    #pragma unroll
    for (int d = 0; d < 32; d++)
        ETs[(size_t)(h * 32 + d) * M_ + tid] = scale * acc3[d];
}

// ============================================================
// Runtime-split 3-product bf16 GEMM (s2 — precision path)
//   C = acc * e1[c] + e2[slab][r,c]
// ============================================================
#define ST 20
__device__ __forceinline__ uint32_t pack_lo2(float lo0, float lo1) {
    uint32_t r;
    asm("cvt.rn.bf16x2.f32 %0, %1, %2;" : "=r"(r) : "f"(lo1), "f"(lo0));
    return r;
}
__device__ __forceinline__ void split_store8(uint32_t* rowp, int woff,
                                             float4 f0, float4 f1)
{
    uint32_t u0 = __float_as_uint(f0.x), u1 = __float_as_uint(f0.y);
    uint32_t u2 = __float_as_uint(f0.z), u3 = __float_as_uint(f0.w);
    uint32_t u4 = __float_as_uint(f1.x), u5 = __float_as_uint(f1.y);
    uint32_t u6 = __float_as_uint(f1.z), u7 = __float_as_uint(f1.w);
    uint32_t h01 = __byte_perm(u0, u1, 0x7632);
    uint32_t h23 = __byte_perm(u2, u3, 0x7632);
    uint32_t h45 = __byte_perm(u4, u5, 0x7632);
    uint32_t h67 = __byte_perm(u6, u7, 0x7632);
    uint32_t l01 = pack_lo2(f0.x - __uint_as_float(u0 & 0xFFFF0000u),
                            f0.y - __uint_as_float(u1 & 0xFFFF0000u));
    uint32_t l23 = pack_lo2(f0.z - __uint_as_float(u2 & 0xFFFF0000u),
                            f0.w - __uint_as_float(u3 & 0xFFFF0000u));
    uint32_t l45 = pack_lo2(f1.x - __uint_as_float(u4 & 0xFFFF0000u),
                            f1.y - __uint_as_float(u5 & 0xFFFF0000u));
    uint32_t l67 = pack_lo2(f1.z - __uint_as_float(u6 & 0xFFFF0000u),
                            f1.w - __uint_as_float(u7 & 0xFFFF0000u));
    *(uint4*)(rowp + woff)     = make_uint4(h01, h23, l01, l23);
    *(uint4*)(rowp + woff + 4) = make_uint4(h45, h67, l45, l67);
}

__global__ void __launch_bounds__(256) bf16_gemm_s2(
    const float* __restrict__ Ab, int lda, long aStr,
    const float* __restrict__ Bb, int ldb, long bStr,
    float* __restrict__ Cb, int ldc, long cStr,
    int K, int Rlim,
    const float* __restrict__ e1,
    const float* __restrict__ e2b, long e2Str)
{
    __shared__ uint32_t sA[2][128 * ST], sB[2][128 * ST];
    int tid = threadIdx.x;
    int slab = blockIdx.z;
    const float* A = Ab + (size_t)slab * aStr;
    const float* B = Bb + (size_t)slab * bStr;
    float*       C = Cb + (size_t)slab * cStr;
    const float* E2 = e2b + (size_t)slab * e2Str;

    int rowBase = blockIdx.x * 128, colBase = blockIdx.y * 128;

    int ldRow = tid >> 1;
    int ldK   = (tid & 1) << 3;
    int woff  = (tid & 1) << 3;
    const float* Arow = A + (size_t)(rowBase + ldRow) * lda + ldK;
    const float* Brow = B + (size_t)(colBase + ldRow) * ldb + ldK;
    bool aValid = (rowBase + ldRow) < Rlim;

    int lane = tid & 31, warp = tid >> 5;
    int wRow = (warp >> 2) << 6;
    int wCol = (warp & 3) << 5;
    int g = lane >> 2, t = lane & 3;

    const int NT = K >> 4;
    const float4 z4 = make_float4(0.f, 0.f, 0.f, 0.f);

    {
        float4 a0 = aValid ? *(const float4*)Arow : z4;
        float4 a1 = aValid ? *(const float4*)(Arow + 4) : z4;
        split_store8(&sA[0][ldRow * ST], woff, a0, a1);
        float4 b0 = *(const float4*)Brow;
        float4 b1 = *(const float4*)(Brow + 4);
        split_store8(&sB[0][ldRow * ST], woff, b0, b1);
    }
    __syncthreads();

    float acc[4][4][4];
    #pragma unroll
    for (int i = 0; i < 4; i++)
        #pragma unroll
        for (int j = 0; j < 4; j++)
            #pragma unroll
            for (int q = 0; q < 4; q++) acc[i][j][q] = 0.f;

    for (int it = 0; it < NT; it++) {
        int cur = it & 1;
        bool more = (it + 1 < NT);
        float4 na0, na1, nb0, nb1;
        if (more) {
            int k0 = (it + 1) << 4;
            na0 = aValid ? *(const float4*)(Arow + k0) : z4;
            na1 = aValid ? *(const float4*)(Arow + k0 + 4) : z4;
            nb0 = *(const float4*)(Brow + k0);
            nb1 = *(const float4*)(Brow + k0 + 4);
        }

        const uint32_t* sa = sA[cur];
        const uint32_t* sb = sB[cur];

        uint4 bv[4];
        #pragma unroll
        for (int nb = 0; nb < 4; nb++)
            bv[nb] = *(const uint4*)(sb + (wCol + (nb << 3) + g) * ST + (t << 2));

        #pragma unroll
        for (int mb = 0; mb < 4; mb++) {
            const uint32_t* r0p = sa + (wRow + (mb << 4) + g) * ST + (t << 2);
            uint4 v0 = *(const uint4*)r0p;
            uint4 v1 = *(const uint4*)(r0p + (ST << 3));
            #pragma unroll
            for (int nb = 0; nb < 4; nb++) {
                mma_bf16(acc[mb][nb], v0.x, v1.x, v0.y, v1.y, bv[nb].z, bv[nb].w);
                mma_bf16(acc[mb][nb], v0.z, v1.z, v0.w, v1.w, bv[nb].x, bv[nb].y);
                mma_bf16(acc[mb][nb], v0.x, v1.x, v0.y, v1.y, bv[nb].x, bv[nb].y);
            }
        }

        if (more) {
            int nxt = cur ^ 1;
            split_store8(&sA[nxt][ldRow * ST], woff, na0, na1);
            split_store8(&sB[nxt][ldRow * ST], woff, nb0, nb1);
        }
        __syncthreads();
    }

    #pragma unroll
    for (int mb = 0; mb < 4; mb++) {
        int r0 = rowBase + wRow + (mb << 4) + g;
        #pragma unroll
        for (int half = 0; half < 2; half++) {
            int r = r0 + half * 8;
            if (r >= Rlim) continue;
            #pragma unroll
            for (int nb = 0; nb < 4; nb++) {
                int c = colBase + wCol + (nb << 3) + (t << 1);
                float vx = acc[mb][nb][half * 2 + 0];
                float vy = acc[mb][nb][half * 2 + 1];
                const float* rr = E2 + (size_t)r * ldc + c;
                vx = vx * e1[c]     + rr[0];
                vy = vy * e1[c + 1] + rr[1];
                *(float2*)(C + (size_t)r * ldc + c) = make_float2(vx, vy);
            }
        }
    }
}

// ============================================================
// SINGLE-product plain-bf16 GEMM (fc1/fc2 — h path, error-immune).
// Inputs bf16x2 u32 (lda/ldb in u32 = cols/2). Natural row storage,
// fragments via LDS.64 using k-permutation (t, t+4) <-> words
// (2t, 2t+1), applied identically to A and B. ST2=8: conflict-free.
//   mode 1: Cp[r, c>>1] = bf16x2(gelu(acc + bias))   (ldc in u32)
//   mode 2: Cf[r, c]    = acc + bias + resid         (ldc in floats)
// ============================================================
#define ST2 8
__global__ void __launch_bounds__(256) bf16_gemm_1b(
    const uint32_t* __restrict__ A, int lda,
    const uint32_t* __restrict__ B, int ldb,
    int K, int Rlim, int mode, int ldc,
    const float* __restrict__ bias,
    const float* __restrict__ resid,
    float* __restrict__ Cf,
    uint32_t* __restrict__ Cp)
{
    __shared__ uint32_t sA[2][128 * ST2], sB[2][128 * ST2];  // 16 KB
    int tid = threadIdx.x;
    int rowBase = blockIdx.x * 128, colBase = blockIdx.y * 128;

    int ldRow = tid >> 1;            // 0..127
    int wq    = (tid & 1) << 2;      // word 0 or 4
    const uint32_t* Arow = A + (size_t)(rowBase + ldRow) * lda + wq;
    const uint32_t* Brow = B + (size_t)(colBase + ldRow) * ldb + wq;
    bool aValid = (rowBase + ldRow) < Rlim;

    int lane = tid & 31, warp = tid >> 5;
    int wRow = (warp >> 2) << 6;     // 0 or 64
    int wCol = (warp & 3) << 5;      // 0,32,64,96
    int g = lane >> 2, t = lane & 3;

    const int NT = K >> 4;
    const uint4 z4 = make_uint4(0u, 0u, 0u, 0u);

    // preload tile 0
    {
        uint4 a = aValid ? *(const uint4*)Arow : z4;
        *(uint4*)(&sA[0][ldRow * ST2 + wq]) = a;
        uint4 b = *(const uint4*)Brow;
        *(uint4*)(&sB[0][ldRow * ST2 + wq]) = b;
    }
    __syncthreads();

    float acc[4][4][4];
    #pragma unroll
    for (int i = 0; i < 4; i++)
        #pragma unroll
        for (int j = 0; j < 4; j++)
            #pragma unroll
            for (int q = 0; q < 4; q++) acc[i][j][q] = 0.f;

    for (int it = 0; it < NT; it++) {
        int cur = it & 1;
        bool more = (it + 1 < NT);
        uint4 na, nb;
        if (more) {
            int k0 = (it + 1) << 3;   // u32 offset
            na = aValid ? *(const uint4*)(Arow + k0) : z4;
            nb = *(const uint4*)(Brow + k0);
        }

        const uint32_t* sa = sA[cur];
        const uint32_t* sb = sB[cur];

        // B fragments: 4x LDS.64
        uint2 bvv[4];
        #pragma unroll
        for (int nbx = 0; nbx < 4; nbx++)
            bvv[nbx] = *(const uint2*)(sb + (wCol + (nbx << 3) + g) * ST2 + (t << 1));

        #pragma unroll
        for (int mb = 0; mb < 4; mb++) {
            const uint32_t* r0p = sa + (wRow + (mb << 4) + g) * ST2 + (t << 1);
            uint2 v0 = *(const uint2*)r0p;
            uint2 v1 = *(const uint2*)(r0p + (ST2 << 3));   // +8 rows
            #pragma unroll
            for (int nbx = 0; nbx < 4; nbx++)
                mma_bf16(acc[mb][nbx], v0.x, v1.x, v0.y, v1.y, bvv[nbx].x, bvv[nbx].y);
        }

        if (more) {
            int nxt = cur ^ 1;
            *(uint4*)(&sA[nxt][ldRow * ST2 + wq]) = na;
            *(uint4*)(&sB[nxt][ldRow * ST2 + wq]) = nb;
        }
        __syncthreads();
    }

    const float inv_sqrt2 = 0.7071067811865475f;
    #pragma unroll
    for (int mb = 0; mb < 4; mb++) {
        int r0 = rowBase + wRow + (mb << 4) + g;
        #pragma unroll
        for (int half = 0; half < 2; half++) {
            int r = r0 + half * 8;
            if (r >= Rlim) continue;
            #pragma unroll
            for (int nbx = 0; nbx < 4; nbx++) {
                int c = colBase + wCol + (nbx << 3) + (t << 1);
                float vx = acc[mb][nbx][half * 2 + 0];
                float vy = acc[mb][nbx][half * 2 + 1];
                if (mode == 1) {
                    vx += bias[c];
                    vy += bias[c + 1];
                    vx = 0.5f * vx * (1.0f + erff(vx * inv_sqrt2));
                    vy = 0.5f * vy * (1.0f + erff(vy * inv_sqrt2));
                    Cp[(size_t)r * ldc + (c >> 1)] = pack_bf2(vx, vy);
                } else {
                    const float* rr = resid + (size_t)r * ldc + c;
                    vx += bias[c]     + rr[0];
                    vy += bias[c + 1] + rr[1];
                    *(float2*)(Cf + (size_t)r * ldc + c) = make_float2(vx, vy);
                }
            }
        }
    }
}

// ============================================================
// Launch
// ============================================================
extern "C" void kernel_launch(void* const* d_in, const int* in_sizes, int n_in,
                              void* d_out, int out_size)
{
    (void)in_sizes; (void)n_in; (void)out_size;
    const float* savespace = (const float*)d_in[1];
    const float* Wqkv      = (const float*)d_in[2];
    const float* Wo        = (const float*)d_in[3];
    const float* ln1_g     = (const float*)d_in[4];
    const float* ln1_b     = (const float*)d_in[5];
    const float* ln2_g     = (const float*)d_in[6];
    const float* ln2_b     = (const float*)d_in[7];
    const float* fc1_w     = (const float*)d_in[8];
    const float* fc1_b     = (const float*)d_in[9];
    const float* fc2_w     = (const float*)d_in[10];
    const float* fc2_b     = (const float*)d_in[11];
    float* out = (float*)d_out;

    float *p_sln, *p_s2, *p_G, *p_Gp, *p_T, *p_ET, *p_ws;
    uint32_t *p_hlnb, *p_h1b, *p_w1b, *p_w2b;
    cudaGetSymbolAddress((void**)&p_sln, g_sln);
    cudaGetSymbolAddress((void**)&p_s2,  g_s2);
    cudaGetSymbolAddress((void**)&p_G,   g_G);
    cudaGetSymbolAddress((void**)&p_Gp,  g_Gp);
    cudaGetSymbolAddress((void**)&p_T,   g_T);
    cudaGetSymbolAddress((void**)&p_ET,  g_ET);
    cudaGetSymbolAddress((void**)&p_ws,  g_wosum);
    cudaGetSymbolAddress((void**)&p_hlnb, g_hlnb);
    cudaGetSymbolAddress((void**)&p_h1b,  g_h1b);
    cudaGetSymbolAddress((void**)&p_w1b,  g_w1b);
    cudaGetSymbolAddress((void**)&p_w2b,  g_w2b);

    const long SLAB = (long)J_ * M_;
    const long MM   = MM_;

    // 1) layernorm1 (fp32 — feeds gram and s2)
    ln_kernel<<<RTOT / 8, 256>>>(savespace, ln1_g, ln1_b, p_sln);
    // 2) pack weights to bf16 (once per launch)
    packw_kernel<<<(FF_ * M_ / 4 + 255) / 256, 256>>>(fc1_w, p_w1b, FF_ * M_ / 4);
    packw_kernel<<<(M_ * FF_ / 4 + 255) / 256, 256>>>(fc2_w, p_w2b, M_ * FF_ / 4);
    // 3) Gram partials + reduce (fp32)
    gram_kernel<<<dim3(4, 4, NSLAB * NCH), 256>>>(p_sln, p_Gp);
    gram_reduce<<<dim3(64, NSLAB), 256>>>(p_Gp, p_G);
    // 4) Wo row sums
    rowsum_kernel<<<32, 256>>>(Wo, p_ws);
    // 5) T = G @ Wv_full^T per slab
    gemm64<<<dim3(4, 4, NSLAB), 256>>>(
        p_G, M_, MM,  Wqkv + 2 * H_ * DH_ * M_, M_, 0,  p_T, M_, MM, M_);
    // 6) finish ET per (head, slab)
    assemble2_kernel<<<dim3(H_, NSLAB), 256>>>(Wqkv, p_T, p_ET);
    // 7) s2 = wosum * (s_ln @ E) + savespace   [3-product bf16 — precision path]
    bf16_gemm_s2<<<dim3(9, 2, NSLAB), 256>>>(
        p_sln, M_, SLAB,  p_ET, M_, MM,  p_s2, M_, SLAB,
        M_, J_, p_ws, savespace, SLAB);
    // 8) layernorm2 -> bf16x2 (h path; error-immune)
    ln_bf16_kernel<<<RTOT / 8, 256>>>(p_s2, ln2_g, ln2_b, p_hlnb);
    // 9) h1 = gelu(hln @ fc1_w^T + b1)   [single bf16]
    bf16_gemm_1b<<<dim3(129, 8), 256>>>(
        p_hlnb, M_ / 2, p_w1b, M_ / 2,
        M_, RTOT, 1, FF_ / 2, fc1_b, (const float*)0, (float*)0, p_h1b);
    // 10) out = h1 @ fc2_w^T + b2 + s2   [single bf16; fp32 residual]
    bf16_gemm_1b<<<dim3(129, 2), 256>>>(
        p_h1b, FF_ / 2, p_w2b, FF_ / 2,
        FF_, RTOT, 2, M_, fc2_b, p_s2, out, (uint32_t*)0);
}

// round 16
// speedup vs baseline: 1.7687x; 1.0572x over previous
#include <cuda_runtime.h>
#include <cuda_bf16.h>
#include <math.h>
#include <cstdint>

// Shapes (fixed by the problem)
#define B_    2
#define I_    8
#define J_    1025
#define M_    256
#define H_    8
#define DH_   32
#define NSLAB 16              // B_*I_
#define RTOT  (NSLAB * J_)    // 16400
#define FF_   1024            // 4*M
#define NCH   5               // gram K-chunks (208 each, J padded to 1040)
#define JPAD  1040
#define KCH   208
#define MM_   (M_ * M_)

typedef unsigned long long u64;

// ---- scratch (static __device__ arrays; no runtime allocation) ----
__device__ float    g_sln[RTOT * M_];
__device__ uint32_t g_slnT[(size_t)NSLAB * M_ * JPAD];  // packed {hi|lo}, transposed
__device__ float    g_s2 [RTOT * M_];
__device__ uint32_t g_hlnb[RTOT * M_ / 2];          // ln2 out, bf16x2
__device__ uint32_t g_h1b [(size_t)RTOT * FF_ / 2]; // gelu(fc1) out, bf16x2
__device__ uint32_t g_w1b [FF_ * M_ / 2];           // fc1_w bf16x2
__device__ uint32_t g_w2b [M_ * FF_ / 2];           // fc2_w bf16x2
__device__ float    g_G  [NSLAB * MM_];
__device__ float    g_Gp [NCH * NSLAB * MM_];
__device__ float    g_T  [NSLAB * MM_];
__device__ float    g_ET [NSLAB * MM_];
__device__ float    g_wosum[M_];

// ---- f32x2 packed-FMA helpers ----
__device__ __forceinline__ u64 dup2(float x) {
    u64 r; asm("mov.b64 %0, {%1,%1};" : "=l"(r) : "f"(x)); return r;
}
__device__ __forceinline__ void fma2(u64& d, u64 a, u64 b) {
    asm("fma.rn.f32x2 %0, %1, %2, %0;" : "+l"(d) : "l"(a), "l"(b));
}
__device__ __forceinline__ float2 unpack2(u64 v) {
    float2 r; asm("mov.b64 {%0,%1}, %2;" : "=f"(r.x), "=f"(r.y) : "l"(v)); return r;
}

// ---- bf16 mma helper (m16n8k16, sm_80+) ----
__device__ __forceinline__ void mma_bf16(float* c,
    uint32_t a0, uint32_t a1, uint32_t a2, uint32_t a3,
    uint32_t b0, uint32_t b1)
{
    asm("mma.sync.aligned.m16n8k16.row.col.f32.bf16.bf16.f32 "
        "{%0,%1,%2,%3}, {%4,%5,%6,%7}, {%8,%9}, {%0,%1,%2,%3};"
        : "+f"(c[0]), "+f"(c[1]), "+f"(c[2]), "+f"(c[3])
        : "r"(a0), "r"(a1), "r"(a2), "r"(a3), "r"(b0), "r"(b1));
}
__device__ __forceinline__ uint32_t pack_bf2(float x, float y) {
    uint32_t r;
    asm("cvt.rn.bf16x2.f32 %0, %1, %2;" : "=r"(r) : "f"(y), "f"(x));
    return r;
}
__device__ __forceinline__ uint32_t pack_lo2(float lo0, float lo1) {
    uint32_t r;
    asm("cvt.rn.bf16x2.f32 %0, %1, %2;" : "=r"(r) : "f"(lo1), "f"(lo0));
    return r;
}
// pack one fp32 into u32: truncated hi in top 16, bf16(lo) in low 16
__device__ __forceinline__ uint32_t pack_split1(float x) {
    uint32_t u = __float_as_uint(x) & 0xFFFF0000u;
    float lo_f = x - __uint_as_float(u);
    __nv_bfloat16 lb = __float2bfloat16(lo_f);
    return u | (uint32_t)*(unsigned short*)&lb;
}

// ============================================================
// LayerNorm, warp-per-row (8 rows per 256-thr block), fp32 out
// ============================================================
__global__ void ln_kernel(const float* __restrict__ x,
                          const float* __restrict__ g,
                          const float* __restrict__ b,
                          float* __restrict__ out)
{
    int warp = threadIdx.x >> 5, lane = threadIdx.x & 31;
    int row = blockIdx.x * 8 + warp;
    const float* xr = x + (size_t)row * M_ + lane * 8;
    float4 v0 = *(const float4*)xr;
    float4 v1 = *(const float4*)(xr + 4);

    float s = v0.x + v0.y + v0.z + v0.w + v1.x + v1.y + v1.z + v1.w;
    #pragma unroll
    for (int o = 16; o > 0; o >>= 1) s += __shfl_xor_sync(0xffffffffu, s, o);
    float mean = s * (1.0f / M_);

    float d0 = v0.x - mean, d1 = v0.y - mean, d2 = v0.z - mean, d3 = v0.w - mean;
    float d4 = v1.x - mean, d5 = v1.y - mean, d6 = v1.z - mean, d7 = v1.w - mean;
    float q = d0*d0 + d1*d1 + d2*d2 + d3*d3 + d4*d4 + d5*d5 + d6*d6 + d7*d7;
    #pragma unroll
    for (int o = 16; o > 0; o >>= 1) q += __shfl_xor_sync(0xffffffffu, q, o);
    float rs = rsqrtf(q * (1.0f / M_) + 1e-5f);

    const float* gp = g + lane * 8;
    const float* bp = b + lane * 8;
    float4 g0 = *(const float4*)gp, g1 = *(const float4*)(gp + 4);
    float4 b0 = *(const float4*)bp, b1 = *(const float4*)(bp + 4);
    float4 o0, o1;
    o0.x = d0*rs*g0.x + b0.x; o0.y = d1*rs*g0.y + b0.y;
    o0.z = d2*rs*g0.z + b0.z; o0.w = d3*rs*g0.w + b0.w;
    o1.x = d4*rs*g1.x + b1.x; o1.y = d5*rs*g1.y + b1.y;
    o1.z = d6*rs*g1.z + b1.z; o1.w = d7*rs*g1.w + b1.w;
    float* op = out + (size_t)row * M_ + lane * 8;
    *(float4*)op = o0;
    *(float4*)(op + 4) = o1;
}

// ============================================================
// LayerNorm, warp-per-row, bf16x2 out (feeds fc1 only)
// ============================================================
__global__ void ln_bf16_kernel(const float* __restrict__ x,
                               const float* __restrict__ g,
                               const float* __restrict__ b,
                               uint32_t* __restrict__ out)
{
    int warp = threadIdx.x >> 5, lane = threadIdx.x & 31;
    int row = blockIdx.x * 8 + warp;
    const float* xr = x + (size_t)row * M_ + lane * 8;
    float4 v0 = *(const float4*)xr;
    float4 v1 = *(const float4*)(xr + 4);

    float s = v0.x + v0.y + v0.z + v0.w + v1.x + v1.y + v1.z + v1.w;
    #pragma unroll
    for (int o = 16; o > 0; o >>= 1) s += __shfl_xor_sync(0xffffffffu, s, o);
    float mean = s * (1.0f / M_);

    float d0 = v0.x - mean, d1 = v0.y - mean, d2 = v0.z - mean, d3 = v0.w - mean;
    float d4 = v1.x - mean, d5 = v1.y - mean, d6 = v1.z - mean, d7 = v1.w - mean;
    float q = d0*d0 + d1*d1 + d2*d2 + d3*d3 + d4*d4 + d5*d5 + d6*d6 + d7*d7;
    #pragma unroll
    for (int o = 16; o > 0; o >>= 1) q += __shfl_xor_sync(0xffffffffu, q, o);
    float rs = rsqrtf(q * (1.0f / M_) + 1e-5f);

    const float* gp = g + lane * 8;
    const float* bp = b + lane * 8;
    float4 g0 = *(const float4*)gp, g1 = *(const float4*)(gp + 4);
    float4 b0 = *(const float4*)bp, b1 = *(const float4*)(bp + 4);
    uint4 p;
    p.x = pack_bf2(d0*rs*g0.x + b0.x, d1*rs*g0.y + b0.y);
    p.y = pack_bf2(d2*rs*g0.z + b0.z, d3*rs*g0.w + b0.w);
    p.z = pack_bf2(d4*rs*g1.x + b1.x, d5*rs*g1.y + b1.y);
    p.w = pack_bf2(d6*rs*g1.z + b1.z, d7*rs*g1.w + b1.w);
    *(uint4*)(out + (size_t)row * (M_ / 2) + lane * 4) = p;
}

// ============================================================
// Weight pack: fp32 -> bf16x2
// ============================================================
__global__ void packw_kernel(const float* __restrict__ src,
                             uint32_t* __restrict__ dst, int n4)
{
    int i = blockIdx.x * 256 + threadIdx.x;
    if (i < n4) {
        float4 v = ((const float4*)src)[i];
        uint2 p;
        p.x = pack_bf2(v.x, v.y);
        p.y = pack_bf2(v.z, v.w);
        ((uint2*)dst)[i] = p;
    }
}

// ============================================================
// Transpose + split-pack: sln[slab][j][m] -> slnT[slab][m][jpad]
// u32 {hi|lo}; j >= J_ zero-padded. 32x32 smem tiles.
// grid: (33 j-tiles, 8 m-tiles, NSLAB), 256 threads.
// ============================================================
__global__ void transpose_pack(const float* __restrict__ sln,
                               uint32_t* __restrict__ slnT)
{
    __shared__ uint32_t tile[32][33];
    int slab = blockIdx.z;
    int j0 = blockIdx.x * 32, m0 = blockIdx.y * 32;
    int tx = threadIdx.x & 31, ty = threadIdx.x >> 5;   // ty: 0..7

    const float* src = sln + (size_t)slab * J_ * M_;
    #pragma unroll
    for (int p = 0; p < 4; p++) {
        int j = j0 + ty + p * 8;
        uint32_t v = 0;
        if (j < J_) v = pack_split1(src[(size_t)j * M_ + m0 + tx]);
        tile[ty + p * 8][tx] = v;
    }
    __syncthreads();
    uint32_t* dst = slnT + (size_t)slab * M_ * JPAD;
    #pragma unroll
    for (int p = 0; p < 4; p++) {
        int m = m0 + ty + p * 8;
        int j = j0 + tx;
        if (j < JPAD) dst[(size_t)m * JPAD + j] = tile[tx][ty + p * 8];
    }
}

// ============================================================
// Wo row sums — one warp per row
// ============================================================
__global__ void rowsum_kernel(const float* __restrict__ Wo, float* __restrict__ ws)
{
    int warp = threadIdx.x >> 5, lane = threadIdx.x & 31;
    int n = blockIdx.x * 8 + warp;
    const float* row = Wo + (size_t)n * M_;
    float s = 0.f;
    #pragma unroll
    for (int m = lane; m < M_; m += 32) s += row[m];
    #pragma unroll
    for (int o = 16; o > 0; o >>= 1) s += __shfl_xor_sync(0xffffffffu, s, o);
    if (lane == 0) ws[n] = s;
}

// ============================================================
// shared loader for pre-split packed inputs: pair-group PRMT
// ============================================================
#define ST 20
__device__ __forceinline__ void prmt_store8(uint32_t* rowp, int woff,
                                            uint4 e0, uint4 e1)
{
    uint32_t h01 = __byte_perm(e0.x, e0.y, 0x7632);
    uint32_t l01 = __byte_perm(e0.x, e0.y, 0x5410);
    uint32_t h23 = __byte_perm(e0.z, e0.w, 0x7632);
    uint32_t l23 = __byte_perm(e0.z, e0.w, 0x5410);
    uint32_t h45 = __byte_perm(e1.x, e1.y, 0x7632);
    uint32_t l45 = __byte_perm(e1.x, e1.y, 0x5410);
    uint32_t h67 = __byte_perm(e1.z, e1.w, 0x7632);
    uint32_t l67 = __byte_perm(e1.z, e1.w, 0x5410);
    *(uint4*)(rowp + woff)     = make_uint4(h01, h23, l01, l23);
    *(uint4*)(rowp + woff + 4) = make_uint4(h45, h67, l45, l67);
}

// ============================================================
// TENSOR-CORE GRAM (3-product bf16): Gp[slab,ch] partial of
// S^T S over k-chunk. A=B=slnT rows. 128x128 tile, symmetric.
// blockIdx.x: 0->(0,0) 1->(0,1) 2->(1,1); blockIdx.z=slab*NCH+ch
// ============================================================
__global__ void __launch_bounds__(256) gram_tc(const uint32_t* __restrict__ slnT,
                                               float* __restrict__ Gp)
{
    __shared__ uint32_t sA[2][128 * ST], sB[2][128 * ST];
    int tid = threadIdx.x;
    int combo = blockIdx.x;
    int bx = (combo == 2) ? 1 : 0;
    int by = (combo == 0) ? 0 : 1;
    int zc = blockIdx.z;
    int slab = zc / NCH, ch = zc - slab * NCH;
    const uint32_t* Ab = slnT + (size_t)slab * M_ * JPAD;
    int p0 = bx << 7, q0 = by << 7;
    int kbase = ch * KCH;

    int ldRow = tid >> 1;
    int ldK   = (tid & 1) << 3;
    int woff  = (tid & 1) << 3;
    const uint32_t* Arow = Ab + (size_t)(p0 + ldRow) * JPAD + kbase + ldK;
    const uint32_t* Brow = Ab + (size_t)(q0 + ldRow) * JPAD + kbase + ldK;

    int lane = tid & 31, warp = tid >> 5;
    int wRow = (warp >> 2) << 6;
    int wCol = (warp & 3) << 5;
    int g = lane >> 2, t = lane & 3;

    const int NT = KCH >> 4;    // 13

    {
        uint4 a0 = *(const uint4*)Arow;
        uint4 a1 = *(const uint4*)(Arow + 4);
        prmt_store8(&sA[0][ldRow * ST], woff, a0, a1);
        uint4 b0 = *(const uint4*)Brow;
        uint4 b1 = *(const uint4*)(Brow + 4);
        prmt_store8(&sB[0][ldRow * ST], woff, b0, b1);
    }
    __syncthreads();

    float acc[4][4][4];
    #pragma unroll
    for (int i = 0; i < 4; i++)
        #pragma unroll
        for (int j = 0; j < 4; j++)
            #pragma unroll
            for (int q = 0; q < 4; q++) acc[i][j][q] = 0.f;

    for (int it = 0; it < NT; it++) {
        int cur = it & 1;
        bool more = (it + 1 < NT);
        uint4 na0, na1, nb0, nb1;
        if (more) {
            int k0 = (it + 1) << 4;
            na0 = *(const uint4*)(Arow + k0);
            na1 = *(const uint4*)(Arow + k0 + 4);
            nb0 = *(const uint4*)(Brow + k0);
            nb1 = *(const uint4*)(Brow + k0 + 4);
        }

        const uint32_t* sa = sA[cur];
        const uint32_t* sb = sB[cur];

        uint4 bv[4];
        #pragma unroll
        for (int nb = 0; nb < 4; nb++)
            bv[nb] = *(const uint4*)(sb + (wCol + (nb << 3) + g) * ST + (t << 2));

        #pragma unroll
        for (int mb = 0; mb < 4; mb++) {
            const uint32_t* r0p = sa + (wRow + (mb << 4) + g) * ST + (t << 2);
            uint4 v0 = *(const uint4*)r0p;
            uint4 v1 = *(const uint4*)(r0p + (ST << 3));
            #pragma unroll
            for (int nb = 0; nb < 4; nb++) {
                mma_bf16(acc[mb][nb], v0.x, v1.x, v0.y, v1.y, bv[nb].z, bv[nb].w);
                mma_bf16(acc[mb][nb], v0.z, v1.z, v0.w, v1.w, bv[nb].x, bv[nb].y);
                mma_bf16(acc[mb][nb], v0.x, v1.x, v0.y, v1.y, bv[nb].x, bv[nb].y);
            }
        }

        if (more) {
            int nxt = cur ^ 1;
            prmt_store8(&sA[nxt][ldRow * ST], woff, na0, na1);
            prmt_store8(&sB[nxt][ldRow * ST], woff, nb0, nb1);
        }
        __syncthreads();
    }

    float* Gs = Gp + (size_t)zc * MM_;
    #pragma unroll
    for (int mb = 0; mb < 4; mb++) {
        int r0 = p0 + wRow + (mb << 4) + g;
        #pragma unroll
        for (int half = 0; half < 2; half++) {
            int r = r0 + half * 8;
            #pragma unroll
            for (int nb = 0; nb < 4; nb++) {
                int c = q0 + wCol + (nb << 3) + (t << 1);
                float vx = acc[mb][nb][half * 2 + 0];
                float vy = acc[mb][nb][half * 2 + 1];
                Gs[(size_t)r * M_ + c]     = vx;
                Gs[(size_t)r * M_ + c + 1] = vy;
                Gs[(size_t)c * M_ + r]       = vx;
                Gs[(size_t)(c + 1) * M_ + r] = vy;
            }
        }
    }
}

// ============================================================
// Gram reduce
// ============================================================
__global__ void gram_reduce(const float* __restrict__ Gp, float* __restrict__ G)
{
    int slab = blockIdx.y;
    int idx = (blockIdx.x * 256 + threadIdx.x) * 4;
    const float* base = Gp + (size_t)slab * NCH * MM_ + idx;
    float4 s = *(const float4*)base;
    #pragma unroll
    for (int ch = 1; ch < NCH; ch++) {
        float4 v = *(const float4*)(base + (size_t)ch * MM_);
        s.x += v.x; s.y += v.y; s.z += v.z; s.w += v.w;
    }
    *(float4*)(G + (size_t)slab * MM_ + idx) = s;
}

// ============================================================
// 64x64 NT GEMM (T = G @ Wv^T)
// ============================================================
__global__ void __launch_bounds__(256) gemm64(
    const float* __restrict__ Ab, int lda, long aStride,
    const float* __restrict__ Bb, int ldb, long bStride,
    float* __restrict__ Cb, int ldc, long cStride, int K)
{
    int slab = blockIdx.z;
    const float* A = Ab + (size_t)slab * aStride;
    const float* B = Bb + (size_t)slab * bStride;
    float*       C = Cb + (size_t)slab * cStride;

    int rowBase = blockIdx.x * 64;
    int colBase = blockIdx.y * 64;

    __shared__ float As[16][64], Bs[16][64];
    int tid = threadIdx.x;
    int lm = tid >> 2;
    int lk = (tid & 3) << 2;
    int tx = tid & 15, ty = tid >> 4;

    u64 acc[4][2] = {};
    for (int k0 = 0; k0 < K; k0 += 16) {
        float4 av = *(const float4*)(A + (size_t)(rowBase + lm) * lda + k0 + lk);
        As[lk + 0][lm] = av.x; As[lk + 1][lm] = av.y;
        As[lk + 2][lm] = av.z; As[lk + 3][lm] = av.w;
        float4 bv = *(const float4*)(B + (size_t)(colBase + lm) * ldb + k0 + lk);
        Bs[lk + 0][lm] = bv.x; Bs[lk + 1][lm] = bv.y;
        Bs[lk + 2][lm] = bv.z; Bs[lk + 3][lm] = bv.w;
        __syncthreads();
        #pragma unroll
        for (int k = 0; k < 16; k++) {
            float4 a = *(const float4*)&As[k][ty << 2];
            ulonglong2 b = *(const ulonglong2*)&Bs[k][tx << 2];
            u64 a2;
            a2 = dup2(a.x); fma2(acc[0][0], a2, b.x); fma2(acc[0][1], a2, b.y);
            a2 = dup2(a.y); fma2(acc[1][0], a2, b.x); fma2(acc[1][1], a2, b.y);
            a2 = dup2(a.z); fma2(acc[2][0], a2, b.x); fma2(acc[2][1], a2, b.y);
            a2 = dup2(a.w); fma2(acc[3][0], a2, b.x); fma2(acc[3][1], a2, b.y);
        }
        __syncthreads();
    }
    #pragma unroll
    for (int i = 0; i < 4; i++) {
        int r = rowBase + (ty << 2) + i;
        #pragma unroll
        for (int j2 = 0; j2 < 2; j2++) {
            int c = colBase + (tx << 2) + j2 * 2;
            float2 v = unpack2(acc[i][j2]);
            *(float2*)(C + (size_t)r * ldc + c) = v;
        }
    }
}

// ============================================================
// Small per-(head,slab) finisher
// ============================================================
__global__ void __launch_bounds__(256) assemble2_kernel(const float* __restrict__ Wqkv,
                                                        const float* __restrict__ T,
                                                        float* __restrict__ ET)
{
    int h = blockIdx.x;
    int slab = blockIdx.y;
    const float* Ts = T + (size_t)slab * MM_;
    const float* Wq = Wqkv + (size_t)(0 * H_ + h) * DH_ * M_;
    const float* Wk = Wqkv + (size_t)(1 * H_ + h) * DH_ * M_;

    __shared__ float sT[256][33];
    __shared__ float ktv[32][33];
    int tid = threadIdx.x;

    {
        int m = tid >> 5, d = tid & 31;
        #pragma unroll
        for (int pass = 0; pass < 32; pass++) {
            int mm = pass * 8 + m;
            sT[mm][d] = Ts[(size_t)mm * M_ + h * 32 + d];
        }
    }
    __syncthreads();

    {
        int d  = tid & 31;
        int e0 = (tid >> 5) << 2;
        float acc4[4] = {0.f, 0.f, 0.f, 0.f};
        for (int m = 0; m < 256; m++) {
            float t = sT[m][d];
            #pragma unroll
            for (int ee = 0; ee < 4; ee++)
                acc4[ee] = fmaf(Wk[(size_t)(e0 + ee) * M_ + m], t, acc4[ee]);
        }
        #pragma unroll
        for (int ee = 0; ee < 4; ee++)
            ktv[e0 + ee][d] = acc4[ee];
    }
    __syncthreads();

    float acc3[32];
    #pragma unroll
    for (int d = 0; d < 32; d++) acc3[d] = 0.f;
    for (int e2 = 0; e2 < 32; e2++) {
        float w = Wq[(size_t)e2 * M_ + tid];
        #pragma unroll
        for (int d = 0; d < 32; d++) acc3[d] = fmaf(w, ktv[e2][d], acc3[d]);
    }
    const float scale = 0.17677669529663687f;
    float* ETs = ET + (size_t)slab * MM_;
    #pragma unroll
    for (int d = 0; d < 32; d++)
        ETs[(size_t)(h * 32 + d) * M_ + tid] = scale * acc3[d];
}

// ============================================================
// Runtime-split 3-product bf16 GEMM (s2 — precision path)
//   C = acc * e1[c] + e2[slab][r,c]
// ============================================================
__device__ __forceinline__ void split_store8(uint32_t* rowp, int woff,
                                             float4 f0, float4 f1)
{
    uint32_t u0 = __float_as_uint(f0.x), u1 = __float_as_uint(f0.y);
    uint32_t u2 = __float_as_uint(f0.z), u3 = __float_as_uint(f0.w);
    uint32_t u4 = __float_as_uint(f1.x), u5 = __float_as_uint(f1.y);
    uint32_t u6 = __float_as_uint(f1.z), u7 = __float_as_uint(f1.w);
    uint32_t h01 = __byte_perm(u0, u1, 0x7632);
    uint32_t h23 = __byte_perm(u2, u3, 0x7632);
    uint32_t h45 = __byte_perm(u4, u5, 0x7632);
    uint32_t h67 = __byte_perm(u6, u7, 0x7632);
    uint32_t l01 = pack_lo2(f0.x - __uint_as_float(u0 & 0xFFFF0000u),
                            f0.y - __uint_as_float(u1 & 0xFFFF0000u));
    uint32_t l23 = pack_lo2(f0.z - __uint_as_float(u2 & 0xFFFF0000u),
                            f0.w - __uint_as_float(u3 & 0xFFFF0000u));
    uint32_t l45 = pack_lo2(f1.x - __uint_as_float(u4 & 0xFFFF0000u),
                            f1.y - __uint_as_float(u5 & 0xFFFF0000u));
    uint32_t l67 = pack_lo2(f1.z - __uint_as_float(u6 & 0xFFFF0000u),
                            f1.w - __uint_as_float(u7 & 0xFFFF0000u));
    *(uint4*)(rowp + woff)     = make_uint4(h01, h23, l01, l23);
    *(uint4*)(rowp + woff + 4) = make_uint4(h45, h67, l45, l67);
}

__global__ void __launch_bounds__(256) bf16_gemm_s2(
    const float* __restrict__ Ab, int lda, long aStr,
    const float* __restrict__ Bb, int ldb, long bStr,
    float* __restrict__ Cb, int ldc, long cStr,
    int K, int Rlim,
    const float* __restrict__ e1,
    const float* __restrict__ e2b, long e2Str)
{
    __shared__ uint32_t sA[2][128 * ST], sB[2][128 * ST];
    int tid = threadIdx.x;
    int slab = blockIdx.z;
    const float* A = Ab + (size_t)slab * aStr;
    const float* B = Bb + (size_t)slab * bStr;
    float*       C = Cb + (size_t)slab * cStr;
    const float* E2 = e2b + (size_t)slab * e2Str;

    int rowBase = blockIdx.x * 128, colBase = blockIdx.y * 128;

    int ldRow = tid >> 1;
    int ldK   = (tid & 1) << 3;
    int woff  = (tid & 1) << 3;
    const float* Arow = A + (size_t)(rowBase + ldRow) * lda + ldK;
    const float* Brow = B + (size_t)(colBase + ldRow) * ldb + ldK;
    bool aValid = (rowBase + ldRow) < Rlim;

    int lane = tid & 31, warp = tid >> 5;
    int wRow = (warp >> 2) << 6;
    int wCol = (warp & 3) << 5;
    int g = lane >> 2, t = lane & 3;

    const int NT = K >> 4;
    const float4 z4 = make_float4(0.f, 0.f, 0.f, 0.f);

    {
        float4 a0 = aValid ? *(const float4*)Arow : z4;
        float4 a1 = aValid ? *(const float4*)(Arow + 4) : z4;
        split_store8(&sA[0][ldRow * ST], woff, a0, a1);
        float4 b0 = *(const float4*)Brow;
        float4 b1 = *(const float4*)(Brow + 4);
        split_store8(&sB[0][ldRow * ST], woff, b0, b1);
    }
    __syncthreads();

    float acc[4][4][4];
    #pragma unroll
    for (int i = 0; i < 4; i++)
        #pragma unroll
        for (int j = 0; j < 4; j++)
            #pragma unroll
            for (int q = 0; q < 4; q++) acc[i][j][q] = 0.f;

    for (int it = 0; it < NT; it++) {
        int cur = it & 1;
        bool more = (it + 1 < NT);
        float4 na0, na1, nb0, nb1;
        if (more) {
            int k0 = (it + 1) << 4;
            na0 = aValid ? *(const float4*)(Arow + k0) : z4;
            na1 = aValid ? *(const float4*)(Arow + k0 + 4) : z4;
            nb0 = *(const float4*)(Brow + k0);
            nb1 = *(const float4*)(Brow + k0 + 4);
        }

        const uint32_t* sa = sA[cur];
        const uint32_t* sb = sB[cur];

        uint4 bv[4];
        #pragma unroll
        for (int nb = 0; nb < 4; nb++)
            bv[nb] = *(const uint4*)(sb + (wCol + (nb << 3) + g) * ST + (t << 2));

        #pragma unroll
        for (int mb = 0; mb < 4; mb++) {
            const uint32_t* r0p = sa + (wRow + (mb << 4) + g) * ST + (t << 2);
            uint4 v0 = *(const uint4*)r0p;
            uint4 v1 = *(const uint4*)(r0p + (ST << 3));
            #pragma unroll
            for (int nb = 0; nb < 4; nb++) {
                mma_bf16(acc[mb][nb], v0.x, v1.x, v0.y, v1.y, bv[nb].z, bv[nb].w);
                mma_bf16(acc[mb][nb], v0.z, v1.z, v0.w, v1.w, bv[nb].x, bv[nb].y);
                mma_bf16(acc[mb][nb], v0.x, v1.x, v0.y, v1.y, bv[nb].x, bv[nb].y);
            }
        }

        if (more) {
            int nxt = cur ^ 1;
            split_store8(&sA[nxt][ldRow * ST], woff, na0, na1);
            split_store8(&sB[nxt][ldRow * ST], woff, nb0, nb1);
        }
        __syncthreads();
    }

    #pragma unroll
    for (int mb = 0; mb < 4; mb++) {
        int r0 = rowBase + wRow + (mb << 4) + g;
        #pragma unroll
        for (int half = 0; half < 2; half++) {
            int r = r0 + half * 8;
            if (r >= Rlim) continue;
            #pragma unroll
            for (int nb = 0; nb < 4; nb++) {
                int c = colBase + wCol + (nb << 3) + (t << 1);
                float vx = acc[mb][nb][half * 2 + 0];
                float vy = acc[mb][nb][half * 2 + 1];
                const float* rr = E2 + (size_t)r * ldc + c;
                vx = vx * e1[c]     + rr[0];
                vy = vy * e1[c + 1] + rr[1];
                *(float2*)(C + (size_t)r * ldc + c) = make_float2(vx, vy);
            }
        }
    }
}

// ============================================================
// SINGLE-product plain-bf16 GEMM (fc1/fc2 — h path, error-immune)
// ============================================================
#define ST2 8
__global__ void __launch_bounds__(256) bf16_gemm_1b(
    const uint32_t* __restrict__ A, int lda,
    const uint32_t* __restrict__ B, int ldb,
    int K, int Rlim, int mode, int ldc,
    const float* __restrict__ bias,
    const float* __restrict__ resid,
    float* __restrict__ Cf,
    uint32_t* __restrict__ Cp)
{
    __shared__ uint32_t sA[2][128 * ST2], sB[2][128 * ST2];
    int tid = threadIdx.x;
    int rowBase = blockIdx.x * 128, colBase = blockIdx.y * 128;

    int ldRow = tid >> 1;
    int wq    = (tid & 1) << 2;
    const uint32_t* Arow = A + (size_t)(rowBase + ldRow) * lda + wq;
    const uint32_t* Brow = B + (size_t)(colBase + ldRow) * ldb + wq;
    bool aValid = (rowBase + ldRow) < Rlim;

    int lane = tid & 31, warp = tid >> 5;
    int wRow = (warp >> 2) << 6;
    int wCol = (warp & 3) << 5;
    int g = lane >> 2, t = lane & 3;

    const int NT = K >> 4;
    const uint4 z4 = make_uint4(0u, 0u, 0u, 0u);

    {
        uint4 a = aValid ? *(const uint4*)Arow : z4;
        *(uint4*)(&sA[0][ldRow * ST2 + wq]) = a;
        uint4 b = *(const uint4*)Brow;
        *(uint4*)(&sB[0][ldRow * ST2 + wq]) = b;
    }
    __syncthreads();

    float acc[4][4][4];
    #pragma unroll
    for (int i = 0; i < 4; i++)
        #pragma unroll
        for (int j = 0; j < 4; j++)
            #pragma unroll
            for (int q = 0; q < 4; q++) acc[i][j][q] = 0.f;

    for (int it = 0; it < NT; it++) {
        int cur = it & 1;
        bool more = (it + 1 < NT);
        uint4 na, nb;
        if (more) {
            int k0 = (it + 1) << 3;
            na = aValid ? *(const uint4*)(Arow + k0) : z4;
            nb = *(const uint4*)(Brow + k0);
        }

        const uint32_t* sa = sA[cur];
        const uint32_t* sb = sB[cur];

        uint2 bvv[4];
        #pragma unroll
        for (int nbx = 0; nbx < 4; nbx++)
            bvv[nbx] = *(const uint2*)(sb + (wCol + (nbx << 3) + g) * ST2 + (t << 1));

        #pragma unroll
        for (int mb = 0; mb < 4; mb++) {
            const uint32_t* r0p = sa + (wRow + (mb << 4) + g) * ST2 + (t << 1);
            uint2 v0 = *(const uint2*)r0p;
            uint2 v1 = *(const uint2*)(r0p + (ST2 << 3));
            #pragma unroll
            for (int nbx = 0; nbx < 4; nbx++)
                mma_bf16(acc[mb][nbx], v0.x, v1.x, v0.y, v1.y, bvv[nbx].x, bvv[nbx].y);
        }

        if (more) {
            int nxt = cur ^ 1;
            *(uint4*)(&sA[nxt][ldRow * ST2 + wq]) = na;
            *(uint4*)(&sB[nxt][ldRow * ST2 + wq]) = nb;
        }
        __syncthreads();
    }

    const float inv_sqrt2 = 0.7071067811865475f;
    #pragma unroll
    for (int mb = 0; mb < 4; mb++) {
        int r0 = rowBase + wRow + (mb << 4) + g;
        #pragma unroll
        for (int half = 0; half < 2; half++) {
            int r = r0 + half * 8;
            if (r >= Rlim) continue;
            #pragma unroll
            for (int nbx = 0; nbx < 4; nbx++) {
                int c = colBase + wCol + (nbx << 3) + (t << 1);
                float vx = acc[mb][nbx][half * 2 + 0];
                float vy = acc[mb][nbx][half * 2 + 1];
                if (mode == 1) {
                    vx += bias[c];
                    vy += bias[c + 1];
                    vx = 0.5f * vx * (1.0f + erff(vx * inv_sqrt2));
                    vy = 0.5f * vy * (1.0f + erff(vy * inv_sqrt2));
                    Cp[(size_t)r * ldc + (c >> 1)] = pack_bf2(vx, vy);
                } else {
                    const float* rr = resid + (size_t)r * ldc + c;
                    vx += bias[c]     + rr[0];
                    vy += bias[c + 1] + rr[1];
                    *(float2*)(Cf + (size_t)r * ldc + c) = make_float2(vx, vy);
                }
            }
        }
    }
}

// ============================================================
// Launch
// ============================================================
extern "C" void kernel_launch(void* const* d_in, const int* in_sizes, int n_in,
                              void* d_out, int out_size)
{
    (void)in_sizes; (void)n_in; (void)out_size;
    const float* savespace = (const float*)d_in[1];
    const float* Wqkv      = (const float*)d_in[2];
    const float* Wo        = (const float*)d_in[3];
    const float* ln1_g     = (const float*)d_in[4];
    const float* ln1_b     = (const float*)d_in[5];
    const float* ln2_g     = (const float*)d_in[6];
    const float* ln2_b     = (const float*)d_in[7];
    const float* fc1_w     = (const float*)d_in[8];
    const float* fc1_b     = (const float*)d_in[9];
    const float* fc2_w     = (const float*)d_in[10];
    const float* fc2_b     = (const float*)d_in[11];
    float* out = (float*)d_out;

    float *p_sln, *p_s2, *p_G, *p_Gp, *p_T, *p_ET, *p_ws;
    uint32_t *p_slnT, *p_hlnb, *p_h1b, *p_w1b, *p_w2b;
    cudaGetSymbolAddress((void**)&p_sln, g_sln);
    cudaGetSymbolAddress((void**)&p_slnT, g_slnT);
    cudaGetSymbolAddress((void**)&p_s2,  g_s2);
    cudaGetSymbolAddress((void**)&p_G,   g_G);
    cudaGetSymbolAddress((void**)&p_Gp,  g_Gp);
    cudaGetSymbolAddress((void**)&p_T,   g_T);
    cudaGetSymbolAddress((void**)&p_ET,  g_ET);
    cudaGetSymbolAddress((void**)&p_ws,  g_wosum);
    cudaGetSymbolAddress((void**)&p_hlnb, g_hlnb);
    cudaGetSymbolAddress((void**)&p_h1b,  g_h1b);
    cudaGetSymbolAddress((void**)&p_w1b,  g_w1b);
    cudaGetSymbolAddress((void**)&p_w2b,  g_w2b);

    const long SLAB = (long)J_ * M_;
    const long MM   = MM_;

    // 1) layernorm1 (fp32 — feeds transpose and s2)
    ln_kernel<<<RTOT / 8, 256>>>(savespace, ln1_g, ln1_b, p_sln);
    // 2) pack weights (independent)
    packw_kernel<<<(FF_ * M_ / 4 + 255) / 256, 256>>>(fc1_w, p_w1b, FF_ * M_ / 4);
    packw_kernel<<<(M_ * FF_ / 4 + 255) / 256, 256>>>(fc2_w, p_w2b, M_ * FF_ / 4);
    // 3) transpose+pack sln -> slnT
    transpose_pack<<<dim3(33, 8, NSLAB), 256>>>(p_sln, p_slnT);
    // 4) tensor-core gram partials + reduce
    gram_tc<<<dim3(3, 1, NSLAB * NCH), 256>>>(p_slnT, p_Gp);
    gram_reduce<<<dim3(64, NSLAB), 256>>>(p_Gp, p_G);
    // 5) Wo row sums
    rowsum_kernel<<<32, 256>>>(Wo, p_ws);
    // 6) T = G @ Wv_full^T per slab
    gemm64<<<dim3(4, 4, NSLAB), 256>>>(
        p_G, M_, MM,  Wqkv + 2 * H_ * DH_ * M_, M_, 0,  p_T, M_, MM, M_);
    // 7) finish ET per (head, slab)
    assemble2_kernel<<<dim3(H_, NSLAB), 256>>>(Wqkv, p_T, p_ET);
    // 8) s2 = wosum * (s_ln @ E) + savespace   [3-product bf16]
    bf16_gemm_s2<<<dim3(9, 2, NSLAB), 256>>>(
        p_sln, M_, SLAB,  p_ET, M_, MM,  p_s2, M_, SLAB,
        M_, J_, p_ws, savespace, SLAB);
    // 9) layernorm2 -> bf16x2
    ln_bf16_kernel<<<RTOT / 8, 256>>>(p_s2, ln2_g, ln2_b, p_hlnb);
    // 10) h1 = gelu(hln @ fc1_w^T + b1)  [single bf16]
    bf16_gemm_1b<<<dim3(129, 8), 256>>>(
        p_hlnb, M_ / 2, p_w1b, M_ / 2,
        M_, RTOT, 1, FF_ / 2, fc1_b, (const float*)0, (float*)0, p_h1b);
    // 11) out = h1 @ fc2_w^T + b2 + s2   [single bf16; fp32 residual]
    bf16_gemm_1b<<<dim3(129, 2), 256>>>(
        p_h1b, FF_ / 2, p_w2b, FF_ / 2,
        FF_, RTOT, 2, M_, fc2_b, p_s2, out, (uint32_t*)0);
}

// round 17
// speedup vs baseline: 1.8179x; 1.0278x over previous
#include <cuda_runtime.h>
#include <cuda_bf16.h>
#include <math.h>
#include <cstdint>

// Shapes (fixed by the problem)
#define B_    2
#define I_    8
#define J_    1025
#define M_    256
#define H_    8
#define DH_   32
#define NSLAB 16              // B_*I_
#define RTOT  (NSLAB * J_)    // 16400
#define FF_   1024            // 4*M
#define NCH   5               // gram K-chunks (208 each, J padded to 1040)
#define JPAD  1040
#define KCH   208
#define MM_   (M_ * M_)

typedef unsigned long long u64;

// ---- scratch (static __device__ arrays; no runtime allocation) ----
__device__ uint32_t g_slnp[RTOT * M_];                  // ln1 out, packed {hi|lo}
__device__ uint32_t g_slnT[(size_t)NSLAB * M_ * JPAD];  // transposed packed
__device__ float    g_s2 [RTOT * M_];
__device__ uint32_t g_hlnb[RTOT * M_ / 2];          // ln2 out, bf16x2
__device__ uint32_t g_h1b [(size_t)RTOT * FF_ / 2]; // gelu(fc1) out, bf16x2
__device__ uint32_t g_w1b [FF_ * M_ / 2];           // fc1_w bf16x2
__device__ uint32_t g_w2b [M_ * FF_ / 2];           // fc2_w bf16x2
__device__ uint32_t g_wvp [M_ * M_];                // Wv packed {hi|lo}
__device__ uint32_t g_Gk  [NSLAB * MM_];            // G packed {hi|lo}
__device__ float    g_Gp  [NCH * NSLAB * MM_];      // gram partials (fp32)
__device__ float    g_T   [NSLAB * MM_];
__device__ uint32_t g_ETp [NSLAB * MM_];            // ET packed {hi|lo}
__device__ float    g_wosum[M_];

// ---- bf16 mma helper (m16n8k16, sm_80+) ----
__device__ __forceinline__ void mma_bf16(float* c,
    uint32_t a0, uint32_t a1, uint32_t a2, uint32_t a3,
    uint32_t b0, uint32_t b1)
{
    asm("mma.sync.aligned.m16n8k16.row.col.f32.bf16.bf16.f32 "
        "{%0,%1,%2,%3}, {%4,%5,%6,%7}, {%8,%9}, {%0,%1,%2,%3};"
        : "+f"(c[0]), "+f"(c[1]), "+f"(c[2]), "+f"(c[3])
        : "r"(a0), "r"(a1), "r"(a2), "r"(a3), "r"(b0), "r"(b1));
}
__device__ __forceinline__ uint32_t pack_bf2(float x, float y) {
    uint32_t r;
    asm("cvt.rn.bf16x2.f32 %0, %1, %2;" : "=r"(r) : "f"(y), "f"(x));
    return r;
}
// pack one fp32 into u32: truncated hi in top 16, bf16(lo) in low 16
__device__ __forceinline__ uint32_t pack_split1(float x) {
    uint32_t u = __float_as_uint(x) & 0xFFFF0000u;
    float lo_f = x - __uint_as_float(u);
    __nv_bfloat16 lb = __float2bfloat16(lo_f);
    return u | (uint32_t)*(unsigned short*)&lb;
}

// ============================================================
// LayerNorm, warp-per-row, PACKED {hi|lo} out (ln1)
// ============================================================
__global__ void ln_pack_kernel(const float* __restrict__ x,
                               const float* __restrict__ g,
                               const float* __restrict__ b,
                               uint32_t* __restrict__ out)
{
    int warp = threadIdx.x >> 5, lane = threadIdx.x & 31;
    int row = blockIdx.x * 8 + warp;
    const float* xr = x + (size_t)row * M_ + lane * 8;
    float4 v0 = *(const float4*)xr;
    float4 v1 = *(const float4*)(xr + 4);

    float s = v0.x + v0.y + v0.z + v0.w + v1.x + v1.y + v1.z + v1.w;
    #pragma unroll
    for (int o = 16; o > 0; o >>= 1) s += __shfl_xor_sync(0xffffffffu, s, o);
    float mean = s * (1.0f / M_);

    float d0 = v0.x - mean, d1 = v0.y - mean, d2 = v0.z - mean, d3 = v0.w - mean;
    float d4 = v1.x - mean, d5 = v1.y - mean, d6 = v1.z - mean, d7 = v1.w - mean;
    float q = d0*d0 + d1*d1 + d2*d2 + d3*d3 + d4*d4 + d5*d5 + d6*d6 + d7*d7;
    #pragma unroll
    for (int o = 16; o > 0; o >>= 1) q += __shfl_xor_sync(0xffffffffu, q, o);
    float rs = rsqrtf(q * (1.0f / M_) + 1e-5f);

    const float* gp = g + lane * 8;
    const float* bp = b + lane * 8;
    float4 g0 = *(const float4*)gp, g1 = *(const float4*)(gp + 4);
    float4 b0 = *(const float4*)bp, b1 = *(const float4*)(bp + 4);
    uint4 p0, p1;
    p0.x = pack_split1(d0*rs*g0.x + b0.x); p0.y = pack_split1(d1*rs*g0.y + b0.y);
    p0.z = pack_split1(d2*rs*g0.z + b0.z); p0.w = pack_split1(d3*rs*g0.w + b0.w);
    p1.x = pack_split1(d4*rs*g1.x + b1.x); p1.y = pack_split1(d5*rs*g1.y + b1.y);
    p1.z = pack_split1(d6*rs*g1.z + b1.z); p1.w = pack_split1(d7*rs*g1.w + b1.w);
    uint32_t* op = out + (size_t)row * M_ + lane * 8;
    *(uint4*)op = p0;
    *(uint4*)(op + 4) = p1;
}

// ============================================================
// LayerNorm, warp-per-row, bf16x2 out (ln2 -> fc1)
// ============================================================
__global__ void ln_bf16_kernel(const float* __restrict__ x,
                               const float* __restrict__ g,
                               const float* __restrict__ b,
                               uint32_t* __restrict__ out)
{
    int warp = threadIdx.x >> 5, lane = threadIdx.x & 31;
    int row = blockIdx.x * 8 + warp;
    const float* xr = x + (size_t)row * M_ + lane * 8;
    float4 v0 = *(const float4*)xr;
    float4 v1 = *(const float4*)(xr + 4);

    float s = v0.x + v0.y + v0.z + v0.w + v1.x + v1.y + v1.z + v1.w;
    #pragma unroll
    for (int o = 16; o > 0; o >>= 1) s += __shfl_xor_sync(0xffffffffu, s, o);
    float mean = s * (1.0f / M_);

    float d0 = v0.x - mean, d1 = v0.y - mean, d2 = v0.z - mean, d3 = v0.w - mean;
    float d4 = v1.x - mean, d5 = v1.y - mean, d6 = v1.z - mean, d7 = v1.w - mean;
    float q = d0*d0 + d1*d1 + d2*d2 + d3*d3 + d4*d4 + d5*d5 + d6*d6 + d7*d7;
    #pragma unroll
    for (int o = 16; o > 0; o >>= 1) q += __shfl_xor_sync(0xffffffffu, q, o);
    float rs = rsqrtf(q * (1.0f / M_) + 1e-5f);

    const float* gp = g + lane * 8;
    const float* bp = b + lane * 8;
    float4 g0 = *(const float4*)gp, g1 = *(const float4*)(gp + 4);
    float4 b0 = *(const float4*)bp, b1 = *(const float4*)(bp + 4);
    uint4 p;
    p.x = pack_bf2(d0*rs*g0.x + b0.x, d1*rs*g0.y + b0.y);
    p.y = pack_bf2(d2*rs*g0.z + b0.z, d3*rs*g0.w + b0.w);
    p.z = pack_bf2(d4*rs*g1.x + b1.x, d5*rs*g1.y + b1.y);
    p.w = pack_bf2(d6*rs*g1.z + b1.z, d7*rs*g1.w + b1.w);
    *(uint4*)(out + (size_t)row * (M_ / 2) + lane * 4) = p;
}

// ============================================================
// Weight packs
// ============================================================
__global__ void packw_kernel(const float* __restrict__ src,
                             uint32_t* __restrict__ dst, int n4)
{
    int i = blockIdx.x * 256 + threadIdx.x;
    if (i < n4) {
        float4 v = ((const float4*)src)[i];
        uint2 p;
        p.x = pack_bf2(v.x, v.y);
        p.y = pack_bf2(v.z, v.w);
        ((uint2*)dst)[i] = p;
    }
}
__global__ void packs_kernel(const float* __restrict__ src,
                             uint32_t* __restrict__ dst, int n4)
{
    int i = blockIdx.x * 256 + threadIdx.x;
    if (i < n4) {
        float4 v = ((const float4*)src)[i];
        uint4 p;
        p.x = pack_split1(v.x); p.y = pack_split1(v.y);
        p.z = pack_split1(v.z); p.w = pack_split1(v.w);
        ((uint4*)dst)[i] = p;
    }
}

// ============================================================
// Transpose packed u32: slnp[slab][j][m] -> slnT[slab][m][jpad]
// ============================================================
__global__ void transpose_u32(const uint32_t* __restrict__ slnp,
                              uint32_t* __restrict__ slnT)
{
    __shared__ uint32_t tile[32][33];
    int slab = blockIdx.z;
    int j0 = blockIdx.x * 32, m0 = blockIdx.y * 32;
    int tx = threadIdx.x & 31, ty = threadIdx.x >> 5;

    const uint32_t* src = slnp + (size_t)slab * J_ * M_;
    #pragma unroll
    for (int p = 0; p < 4; p++) {
        int j = j0 + ty + p * 8;
        uint32_t v = 0;
        if (j < J_) v = src[(size_t)j * M_ + m0 + tx];
        tile[ty + p * 8][tx] = v;
    }
    __syncthreads();
    uint32_t* dst = slnT + (size_t)slab * M_ * JPAD;
    #pragma unroll
    for (int p = 0; p < 4; p++) {
        int m = m0 + ty + p * 8;
        int j = j0 + tx;
        if (j < JPAD) dst[(size_t)m * JPAD + j] = tile[tx][ty + p * 8];
    }
}

// ============================================================
// Wo row sums — one warp per row
// ============================================================
__global__ void rowsum_kernel(const float* __restrict__ Wo, float* __restrict__ ws)
{
    int warp = threadIdx.x >> 5, lane = threadIdx.x & 31;
    int n = blockIdx.x * 8 + warp;
    const float* row = Wo + (size_t)n * M_;
    float s = 0.f;
    #pragma unroll
    for (int m = lane; m < M_; m += 32) s += row[m];
    #pragma unroll
    for (int o = 16; o > 0; o >>= 1) s += __shfl_xor_sync(0xffffffffu, s, o);
    if (lane == 0) ws[n] = s;
}

// ============================================================
// pair-group PRMT loader (pre-split packed inputs)
// ============================================================
#define ST 20
__device__ __forceinline__ void prmt_store8(uint32_t* rowp, int woff,
                                            uint4 e0, uint4 e1)
{
    uint32_t h01 = __byte_perm(e0.x, e0.y, 0x7632);
    uint32_t l01 = __byte_perm(e0.x, e0.y, 0x5410);
    uint32_t h23 = __byte_perm(e0.z, e0.w, 0x7632);
    uint32_t l23 = __byte_perm(e0.z, e0.w, 0x5410);
    uint32_t h45 = __byte_perm(e1.x, e1.y, 0x7632);
    uint32_t l45 = __byte_perm(e1.x, e1.y, 0x5410);
    uint32_t h67 = __byte_perm(e1.z, e1.w, 0x7632);
    uint32_t l67 = __byte_perm(e1.z, e1.w, 0x5410);
    *(uint4*)(rowp + woff)     = make_uint4(h01, h23, l01, l23);
    *(uint4*)(rowp + woff + 4) = make_uint4(h45, h67, l45, l67);
}

// ============================================================
// TENSOR-CORE GRAM (3-product): partials over k-chunk
// ============================================================
__global__ void __launch_bounds__(256) gram_tc(const uint32_t* __restrict__ slnT,
                                               float* __restrict__ Gp)
{
    __shared__ uint32_t sA[2][128 * ST], sB[2][128 * ST];
    int tid = threadIdx.x;
    int combo = blockIdx.x;
    int bx = (combo == 2) ? 1 : 0;
    int by = (combo == 0) ? 0 : 1;
    int zc = blockIdx.z;
    int slab = zc / NCH, ch = zc - slab * NCH;
    const uint32_t* Ab = slnT + (size_t)slab * M_ * JPAD;
    int p0 = bx << 7, q0 = by << 7;
    int kbase = ch * KCH;

    int ldRow = tid >> 1;
    int ldK   = (tid & 1) << 3;
    int woff  = (tid & 1) << 3;
    const uint32_t* Arow = Ab + (size_t)(p0 + ldRow) * JPAD + kbase + ldK;
    const uint32_t* Brow = Ab + (size_t)(q0 + ldRow) * JPAD + kbase + ldK;

    int lane = tid & 31, warp = tid >> 5;
    int wRow = (warp >> 2) << 6;
    int wCol = (warp & 3) << 5;
    int g = lane >> 2, t = lane & 3;

    const int NT = KCH >> 4;

    {
        uint4 a0 = *(const uint4*)Arow;
        uint4 a1 = *(const uint4*)(Arow + 4);
        prmt_store8(&sA[0][ldRow * ST], woff, a0, a1);
        uint4 b0 = *(const uint4*)Brow;
        uint4 b1 = *(const uint4*)(Brow + 4);
        prmt_store8(&sB[0][ldRow * ST], woff, b0, b1);
    }
    __syncthreads();

    float acc[4][4][4];
    #pragma unroll
    for (int i = 0; i < 4; i++)
        #pragma unroll
        for (int j = 0; j < 4; j++)
            #pragma unroll
            for (int q = 0; q < 4; q++) acc[i][j][q] = 0.f;

    for (int it = 0; it < NT; it++) {
        int cur = it & 1;
        bool more = (it + 1 < NT);
        uint4 na0, na1, nb0, nb1;
        if (more) {
            int k0 = (it + 1) << 4;
            na0 = *(const uint4*)(Arow + k0);
            na1 = *(const uint4*)(Arow + k0 + 4);
            nb0 = *(const uint4*)(Brow + k0);
            nb1 = *(const uint4*)(Brow + k0 + 4);
        }

        const uint32_t* sa = sA[cur];
        const uint32_t* sb = sB[cur];

        uint4 bv[4];
        #pragma unroll
        for (int nb = 0; nb < 4; nb++)
            bv[nb] = *(const uint4*)(sb + (wCol + (nb << 3) + g) * ST + (t << 2));

        #pragma unroll
        for (int mb = 0; mb < 4; mb++) {
            const uint32_t* r0p = sa + (wRow + (mb << 4) + g) * ST + (t << 2);
            uint4 v0 = *(const uint4*)r0p;
            uint4 v1 = *(const uint4*)(r0p + (ST << 3));
            #pragma unroll
            for (int nb = 0; nb < 4; nb++) {
                mma_bf16(acc[mb][nb], v0.x, v1.x, v0.y, v1.y, bv[nb].z, bv[nb].w);
                mma_bf16(acc[mb][nb], v0.z, v1.z, v0.w, v1.w, bv[nb].x, bv[nb].y);
                mma_bf16(acc[mb][nb], v0.x, v1.x, v0.y, v1.y, bv[nb].x, bv[nb].y);
            }
        }

        if (more) {
            int nxt = cur ^ 1;
            prmt_store8(&sA[nxt][ldRow * ST], woff, na0, na1);
            prmt_store8(&sB[nxt][ldRow * ST], woff, nb0, nb1);
        }
        __syncthreads();
    }

    float* Gs = Gp + (size_t)zc * MM_;
    #pragma unroll
    for (int mb = 0; mb < 4; mb++) {
        int r0 = p0 + wRow + (mb << 4) + g;
        #pragma unroll
        for (int half = 0; half < 2; half++) {
            int r = r0 + half * 8;
            #pragma unroll
            for (int nb = 0; nb < 4; nb++) {
                int c = q0 + wCol + (nb << 3) + (t << 1);
                float vx = acc[mb][nb][half * 2 + 0];
                float vy = acc[mb][nb][half * 2 + 1];
                Gs[(size_t)r * M_ + c]     = vx;
                Gs[(size_t)r * M_ + c + 1] = vy;
                Gs[(size_t)c * M_ + r]       = vx;
                Gs[(size_t)(c + 1) * M_ + r] = vy;
            }
        }
    }
}

// ============================================================
// Gram reduce -> packed G
// ============================================================
__global__ void gram_reduce_pack(const float* __restrict__ Gp,
                                 uint32_t* __restrict__ Gk)
{
    int slab = blockIdx.y;
    int idx = (blockIdx.x * 256 + threadIdx.x) * 4;
    const float* base = Gp + (size_t)slab * NCH * MM_ + idx;
    float4 s = *(const float4*)base;
    #pragma unroll
    for (int ch = 1; ch < NCH; ch++) {
        float4 v = *(const float4*)(base + (size_t)ch * MM_);
        s.x += v.x; s.y += v.y; s.z += v.z; s.w += v.w;
    }
    uint4 p;
    p.x = pack_split1(s.x); p.y = pack_split1(s.y);
    p.z = pack_split1(s.z); p.w = pack_split1(s.w);
    *(uint4*)(Gk + (size_t)slab * MM_ + idx) = p;
}

// ============================================================
// Unified pre-split 3-product bf16 GEMM (batched):
//   mode 0: C = acc * e1[c] + e2[slab][r,c]   (s2)
//   mode 3: C = acc                           (T = G @ Wv^T)
// ============================================================
__global__ void __launch_bounds__(256) bf16_gemm_ps3(
    const uint32_t* __restrict__ Ab, int lda, long aStr,
    const uint32_t* __restrict__ Bb, int ldb, long bStr,
    float* __restrict__ Cb, int ldc, long cStr,
    int K, int Rlim, int mode,
    const float* __restrict__ e1,
    const float* __restrict__ e2b, long e2Str)
{
    __shared__ uint32_t sA[2][128 * ST], sB[2][128 * ST];
    int tid = threadIdx.x;
    int slab = blockIdx.z;
    const uint32_t* A = Ab + (size_t)slab * aStr;
    const uint32_t* B = Bb + (size_t)slab * bStr;
    float*           C = Cb + (size_t)slab * cStr;
    const float* E2 = e2b ? (e2b + (size_t)slab * e2Str) : (const float*)0;

    int rowBase = blockIdx.x * 128, colBase = blockIdx.y * 128;

    int ldRow = tid >> 1;
    int ldK   = (tid & 1) << 3;
    int woff  = (tid & 1) << 3;
    const uint32_t* Arow = A + (size_t)(rowBase + ldRow) * lda + ldK;
    const uint32_t* Brow = B + (size_t)(colBase + ldRow) * ldb + ldK;
    bool aValid = (rowBase + ldRow) < Rlim;

    int lane = tid & 31, warp = tid >> 5;
    int wRow = (warp >> 2) << 6;
    int wCol = (warp & 3) << 5;
    int g = lane >> 2, t = lane & 3;

    const int NT = K >> 4;
    const uint4 z4 = make_uint4(0u, 0u, 0u, 0u);

    {
        uint4 a0 = aValid ? *(const uint4*)Arow : z4;
        uint4 a1 = aValid ? *(const uint4*)(Arow + 4) : z4;
        prmt_store8(&sA[0][ldRow * ST], woff, a0, a1);
        uint4 b0 = *(const uint4*)Brow;
        uint4 b1 = *(const uint4*)(Brow + 4);
        prmt_store8(&sB[0][ldRow * ST], woff, b0, b1);
    }
    __syncthreads();

    float acc[4][4][4];
    #pragma unroll
    for (int i = 0; i < 4; i++)
        #pragma unroll
        for (int j = 0; j < 4; j++)
            #pragma unroll
            for (int q = 0; q < 4; q++) acc[i][j][q] = 0.f;

    for (int it = 0; it < NT; it++) {
        int cur = it & 1;
        bool more = (it + 1 < NT);
        uint4 na0, na1, nb0, nb1;
        if (more) {
            int k0 = (it + 1) << 4;
            na0 = aValid ? *(const uint4*)(Arow + k0) : z4;
            na1 = aValid ? *(const uint4*)(Arow + k0 + 4) : z4;
            nb0 = *(const uint4*)(Brow + k0);
            nb1 = *(const uint4*)(Brow + k0 + 4);
        }

        const uint32_t* sa = sA[cur];
        const uint32_t* sb = sB[cur];

        uint4 bv[4];
        #pragma unroll
        for (int nb = 0; nb < 4; nb++)
            bv[nb] = *(const uint4*)(sb + (wCol + (nb << 3) + g) * ST + (t << 2));

        #pragma unroll
        for (int mb = 0; mb < 4; mb++) {
            const uint32_t* r0p = sa + (wRow + (mb << 4) + g) * ST + (t << 2);
            uint4 v0 = *(const uint4*)r0p;
            uint4 v1 = *(const uint4*)(r0p + (ST << 3));
            #pragma unroll
            for (int nb = 0; nb < 4; nb++) {
                mma_bf16(acc[mb][nb], v0.x, v1.x, v0.y, v1.y, bv[nb].z, bv[nb].w);
                mma_bf16(acc[mb][nb], v0.z, v1.z, v0.w, v1.w, bv[nb].x, bv[nb].y);
                mma_bf16(acc[mb][nb], v0.x, v1.x, v0.y, v1.y, bv[nb].x, bv[nb].y);
            }
        }

        if (more) {
            int nxt = cur ^ 1;
            prmt_store8(&sA[nxt][ldRow * ST], woff, na0, na1);
            prmt_store8(&sB[nxt][ldRow * ST], woff, nb0, nb1);
        }
        __syncthreads();
    }

    #pragma unroll
    for (int mb = 0; mb < 4; mb++) {
        int r0 = rowBase + wRow + (mb << 4) + g;
        #pragma unroll
        for (int half = 0; half < 2; half++) {
            int r = r0 + half * 8;
            if (r >= Rlim) continue;
            #pragma unroll
            for (int nb = 0; nb < 4; nb++) {
                int c = colBase + wCol + (nb << 3) + (t << 1);
                float vx = acc[mb][nb][half * 2 + 0];
                float vy = acc[mb][nb][half * 2 + 1];
                if (mode == 0) {
                    const float* rr = E2 + (size_t)r * ldc + c;
                    vx = vx * e1[c]     + rr[0];
                    vy = vy * e1[c + 1] + rr[1];
                }
                *(float2*)(C + (size_t)r * ldc + c) = make_float2(vx, vy);
            }
        }
    }
}

// ============================================================
// Small per-(head,slab) finisher -> packed ET
// ============================================================
__global__ void __launch_bounds__(256) assemble2_kernel(const float* __restrict__ Wqkv,
                                                        const float* __restrict__ T,
                                                        uint32_t* __restrict__ ETp)
{
    int h = blockIdx.x;
    int slab = blockIdx.y;
    const float* Ts = T + (size_t)slab * MM_;
    const float* Wq = Wqkv + (size_t)(0 * H_ + h) * DH_ * M_;
    const float* Wk = Wqkv + (size_t)(1 * H_ + h) * DH_ * M_;

    __shared__ float sT[256][33];
    __shared__ float ktv[32][33];
    int tid = threadIdx.x;

    {
        int m = tid >> 5, d = tid & 31;
        #pragma unroll
        for (int pass = 0; pass < 32; pass++) {
            int mm = pass * 8 + m;
            sT[mm][d] = Ts[(size_t)mm * M_ + h * 32 + d];
        }
    }
    __syncthreads();

    {
        int d  = tid & 31;
        int e0 = (tid >> 5) << 2;
        float acc4[4] = {0.f, 0.f, 0.f, 0.f};
        for (int m = 0; m < 256; m++) {
            float t = sT[m][d];
            #pragma unroll
            for (int ee = 0; ee < 4; ee++)
                acc4[ee] = fmaf(Wk[(size_t)(e0 + ee) * M_ + m], t, acc4[ee]);
        }
        #pragma unroll
        for (int ee = 0; ee < 4; ee++)
            ktv[e0 + ee][d] = acc4[ee];
    }
    __syncthreads();

    float acc3[32];
    #pragma unroll
    for (int d = 0; d < 32; d++) acc3[d] = 0.f;
    for (int e2 = 0; e2 < 32; e2++) {
        float w = Wq[(size_t)e2 * M_ + tid];
        #pragma unroll
        for (int d = 0; d < 32; d++) acc3[d] = fmaf(w, ktv[e2][d], acc3[d]);
    }
    const float scale = 0.17677669529663687f;
    uint32_t* ETs = ETp + (size_t)slab * MM_;
    #pragma unroll
    for (int d = 0; d < 32; d++)
        ETs[(size_t)(h * 32 + d) * M_ + tid] = pack_split1(scale * acc3[d]);
}

// ============================================================
// SINGLE-product plain-bf16 GEMM (fc1/fc2 — h path)
// ============================================================
#define ST2 8
__global__ void __launch_bounds__(256) bf16_gemm_1b(
    const uint32_t* __restrict__ A, int lda,
    const uint32_t* __restrict__ B, int ldb,
    int K, int Rlim, int mode, int ldc,
    const float* __restrict__ bias,
    const float* __restrict__ resid,
    float* __restrict__ Cf,
    uint32_t* __restrict__ Cp)
{
    __shared__ uint32_t sA[2][128 * ST2], sB[2][128 * ST2];
    int tid = threadIdx.x;
    int rowBase = blockIdx.x * 128, colBase = blockIdx.y * 128;

    int ldRow = tid >> 1;
    int wq    = (tid & 1) << 2;
    const uint32_t* Arow = A + (size_t)(rowBase + ldRow) * lda + wq;
    const uint32_t* Brow = B + (size_t)(colBase + ldRow) * ldb + wq;
    bool aValid = (rowBase + ldRow) < Rlim;

    int lane = tid & 31, warp = tid >> 5;
    int wRow = (warp >> 2) << 6;
    int wCol = (warp & 3) << 5;
    int g = lane >> 2, t = lane & 3;

    const int NT = K >> 4;
    const uint4 z4 = make_uint4(0u, 0u, 0u, 0u);

    {
        uint4 a = aValid ? *(const uint4*)Arow : z4;
        *(uint4*)(&sA[0][ldRow * ST2 + wq]) = a;
        uint4 b = *(const uint4*)Brow;
        *(uint4*)(&sB[0][ldRow * ST2 + wq]) = b;
    }
    __syncthreads();

    float acc[4][4][4];
    #pragma unroll
    for (int i = 0; i < 4; i++)
        #pragma unroll
        for (int j = 0; j < 4; j++)
            #pragma unroll
            for (int q = 0; q < 4; q++) acc[i][j][q] = 0.f;

    for (int it = 0; it < NT; it++) {
        int cur = it & 1;
        bool more = (it + 1 < NT);
        uint4 na, nb;
        if (more) {
            int k0 = (it + 1) << 3;
            na = aValid ? *(const uint4*)(Arow + k0) : z4;
            nb = *(const uint4*)(Brow + k0);
        }

        const uint32_t* sa = sA[cur];
        const uint32_t* sb = sB[cur];

        uint2 bvv[4];
        #pragma unroll
        for (int nbx = 0; nbx < 4; nbx++)
            bvv[nbx] = *(const uint2*)(sb + (wCol + (nbx << 3) + g) * ST2 + (t << 1));

        #pragma unroll
        for (int mb = 0; mb < 4; mb++) {
            const uint32_t* r0p = sa + (wRow + (mb << 4) + g) * ST2 + (t << 1);
            uint2 v0 = *(const uint2*)r0p;
            uint2 v1 = *(const uint2*)(r0p + (ST2 << 3));
            #pragma unroll
            for (int nbx = 0; nbx < 4; nbx++)
                mma_bf16(acc[mb][nbx], v0.x, v1.x, v0.y, v1.y, bvv[nbx].x, bvv[nbx].y);
        }

        if (more) {
            int nxt = cur ^ 1;
            *(uint4*)(&sA[nxt][ldRow * ST2 + wq]) = na;
            *(uint4*)(&sB[nxt][ldRow * ST2 + wq]) = nb;
        }
        __syncthreads();
    }

    const float inv_sqrt2 = 0.7071067811865475f;
    #pragma unroll
    for (int mb = 0; mb < 4; mb++) {
        int r0 = rowBase + wRow + (mb << 4) + g;
        #pragma unroll
        for (int half = 0; half < 2; half++) {
            int r = r0 + half * 8;
            if (r >= Rlim) continue;
            #pragma unroll
            for (int nbx = 0; nbx < 4; nbx++) {
                int c = colBase + wCol + (nbx << 3) + (t << 1);
                float vx = acc[mb][nbx][half * 2 + 0];
                float vy = acc[mb][nbx][half * 2 + 1];
                if (mode == 1) {
                    vx += bias[c];
                    vy += bias[c + 1];
                    vx = 0.5f * vx * (1.0f + erff(vx * inv_sqrt2));
                    vy = 0.5f * vy * (1.0f + erff(vy * inv_sqrt2));
                    Cp[(size_t)r * ldc + (c >> 1)] = pack_bf2(vx, vy);
                } else {
                    const float* rr = resid + (size_t)r * ldc + c;
                    vx += bias[c]     + rr[0];
                    vy += bias[c + 1] + rr[1];
                    *(float2*)(Cf + (size_t)r * ldc + c) = make_float2(vx, vy);
                }
            }
        }
    }
}

// ============================================================
// Launch
// ============================================================
extern "C" void kernel_launch(void* const* d_in, const int* in_sizes, int n_in,
                              void* d_out, int out_size)
{
    (void)in_sizes; (void)n_in; (void)out_size;
    const float* savespace = (const float*)d_in[1];
    const float* Wqkv      = (const float*)d_in[2];
    const float* Wo        = (const float*)d_in[3];
    const float* ln1_g     = (const float*)d_in[4];
    const float* ln1_b     = (const float*)d_in[5];
    const float* ln2_g     = (const float*)d_in[6];
    const float* ln2_b     = (const float*)d_in[7];
    const float* fc1_w     = (const float*)d_in[8];
    const float* fc1_b     = (const float*)d_in[9];
    const float* fc2_w     = (const float*)d_in[10];
    const float* fc2_b     = (const float*)d_in[11];
    float* out = (float*)d_out;

    float *p_s2, *p_Gp, *p_T, *p_ws;
    uint32_t *p_slnp, *p_slnT, *p_hlnb, *p_h1b, *p_w1b, *p_w2b, *p_wvp, *p_Gk, *p_ETp;
    cudaGetSymbolAddress((void**)&p_slnp, g_slnp);
    cudaGetSymbolAddress((void**)&p_slnT, g_slnT);
    cudaGetSymbolAddress((void**)&p_s2,  g_s2);
    cudaGetSymbolAddress((void**)&p_Gp,  g_Gp);
    cudaGetSymbolAddress((void**)&p_Gk,  g_Gk);
    cudaGetSymbolAddress((void**)&p_T,   g_T);
    cudaGetSymbolAddress((void**)&p_ETp, g_ETp);
    cudaGetSymbolAddress((void**)&p_ws,  g_wosum);
    cudaGetSymbolAddress((void**)&p_hlnb, g_hlnb);
    cudaGetSymbolAddress((void**)&p_h1b,  g_h1b);
    cudaGetSymbolAddress((void**)&p_w1b,  g_w1b);
    cudaGetSymbolAddress((void**)&p_w2b,  g_w2b);
    cudaGetSymbolAddress((void**)&p_wvp,  g_wvp);

    const long SLAB = (long)J_ * M_;
    const long MM   = MM_;

    // 1) layernorm1 -> packed
    ln_pack_kernel<<<RTOT / 8, 256>>>(savespace, ln1_g, ln1_b, p_slnp);
    // 2) weight packs (independent)
    packw_kernel<<<(FF_ * M_ / 4 + 255) / 256, 256>>>(fc1_w, p_w1b, FF_ * M_ / 4);
    packw_kernel<<<(M_ * FF_ / 4 + 255) / 256, 256>>>(fc2_w, p_w2b, M_ * FF_ / 4);
    packs_kernel<<<(M_ * M_ / 4 + 255) / 256, 256>>>(
        Wqkv + 2 * H_ * DH_ * M_, p_wvp, M_ * M_ / 4);
    // 3) transpose packed sln -> slnT
    transpose_u32<<<dim3(33, 8, NSLAB), 256>>>(p_slnp, p_slnT);
    // 4) tensor-core gram partials + reduce (packed G out)
    gram_tc<<<dim3(3, 1, NSLAB * NCH), 256>>>(p_slnT, p_Gp);
    gram_reduce_pack<<<dim3(64, NSLAB), 256>>>(p_Gp, p_Gk);
    // 5) Wo row sums
    rowsum_kernel<<<32, 256>>>(Wo, p_ws);
    // 6) T = G @ Wv^T per slab   [3-product packed, mode 3]
    bf16_gemm_ps3<<<dim3(2, 2, NSLAB), 256>>>(
        p_Gk, M_, MM,  p_wvp, M_, 0,  p_T, M_, MM,
        M_, M_, 3, (const float*)0, (const float*)0, 0);
    // 7) finish ET per (head, slab) -> packed
    assemble2_kernel<<<dim3(H_, NSLAB), 256>>>(Wqkv, p_T, p_ETp);
    // 8) s2 = wosum * (s_ln @ E) + savespace   [3-product packed, mode 0]
    bf16_gemm_ps3<<<dim3(9, 2, NSLAB), 256>>>(
        p_slnp, M_, SLAB,  p_ETp, M_, MM,  p_s2, M_, SLAB,
        M_, J_, 0, p_ws, savespace, SLAB);
    // 9) layernorm2 -> bf16x2
    ln_bf16_kernel<<<RTOT / 8, 256>>>(p_s2, ln2_g, ln2_b, p_hlnb);
    // 10) h1 = gelu(hln @ fc1_w^T + b1)  [single bf16]
    bf16_gemm_1b<<<dim3(129, 8), 256>>>(
        p_hlnb, M_ / 2, p_w1b, M_ / 2,
        M_, RTOT, 1, FF_ / 2, fc1_b, (const float*)0, (float*)0, p_h1b);
    // 11) out = h1 @ fc2_w^T + b2 + s2   [single bf16; fp32 residual]
    bf16_gemm_1b<<<dim3(129, 2), 256>>>(
        p_h1b, FF_ / 2, p_w2b, FF_ / 2,
        FF_, RTOT, 2, M_, fc2_b, p_s2, out, (uint32_t*)0);
}